// round 6
// baseline (speedup 1.0000x reference)
#include <cuda_runtime.h>
#include <cuda_bf16.h>
#include <cstdint>

#define EPS 1e-5f
#define NGRAPH 128
#define EMAX 800000
#define NMAX 50000

// ---------------- scratch (__device__ globals; no allocation allowed) -------
__device__ int g_is64_bt;
__device__ int g_nodeCnt[NMAX];
__device__ int g_nodeOff[NMAX];
__device__ int g_cursorN[NMAX];
__device__ int g_off[NGRAPH + 1];
__device__ int g_col[EMAX];
__device__ int g_row[EMAX];
__device__ int g_perm[EMAX];
__device__ int g_segS[EMAX];
__device__ int g_colS[EMAX];
__device__ int g_rowS[EMAX];
__device__ __align__(16) float g_P[NMAX * 256];   // emb @ W1[:64 ,:]
__device__ __align__(16) float g_Q[NMAX * 256];   // emb @ W1[64:,:]
__device__ __align__(16) float g_h2[(size_t)EMAX * 64];
__device__ __align__(16) float g_mean1[NGRAPH * 256];
__device__ __align__(16) float g_rstd1[NGRAPH * 256];
__device__ __align__(16) float g_mean2[NGRAPH * 64];
__device__ __align__(16) float g_rstd2[NGRAPH * 64];
// W2 pre-split bf16 hi/lo, packed b32: [kc 8][n 64][k2 16]
__device__ __align__(16) uint32_t g_W2ph[8192];
__device__ __align__(16) uint32_t g_W2pl[8192];

// ---------------- helpers ----------------------------------------------------
__device__ __forceinline__ unsigned long long ffma2(unsigned long long a,
                                                    unsigned long long b,
                                                    unsigned long long c) {
    unsigned long long d;
    asm("fma.rn.f32x2 %0, %1, %2, %3;" : "=l"(d) : "l"(a), "l"(b), "l"(c));
    return d;
}
__device__ __forceinline__ unsigned long long pack2(float x) {
    unsigned long long d;
    asm("mov.b64 %0, {%1, %1};" : "=l"(d) : "f"(x));
    return d;
}
__device__ __forceinline__ uint32_t pkbf(float a, float b) {
    __nv_bfloat162 h = __floats2bfloat162_rn(a, b);
    return *(uint32_t*)&h;
}
__device__ __forceinline__ void bsplit(float v, float& hi, float& lo) {
    __nv_bfloat16 h = __float2bfloat16(v);
    hi = __bfloat162float(h);
    lo = v - hi;
}
__device__ __forceinline__ void mma16816(float* c, uint32_t a0, uint32_t a1,
                                         uint32_t a2, uint32_t a3,
                                         uint32_t b0, uint32_t b1) {
    asm volatile(
        "mma.sync.aligned.m16n8k16.row.col.f32.bf16.bf16.f32 "
        "{%0,%1,%2,%3}, {%4,%5,%6,%7}, {%8,%9}, {%0,%1,%2,%3};"
        : "+f"(c[0]), "+f"(c[1]), "+f"(c[2]), "+f"(c[3])
        : "r"(a0), "r"(a1), "r"(a2), "r"(a3), "r"(b0), "r"(b1));
}
__device__ __forceinline__ void cpasync16(void* dst, const void* src) {
    unsigned sa = (unsigned)__cvta_generic_to_shared(dst);
    asm volatile("cp.async.cg.shared.global [%0], [%1], 16;"
                 :: "r"(sa), "l"(src) : "memory");
}

// ---------------- K: W2 bf16 hi/lo pre-split ----------------------------------
__global__ void k_w2cvt(const float* __restrict__ W2) {
    int i = blockIdx.x * 256 + threadIdx.x;   // 8192
    if (i < 8192) {
        int kc = i >> 10, n = (i >> 4) & 63, k2 = i & 15;
        int kk = kc * 32 + k2 * 2;
        float wa = W2[kk * 64 + n];
        float wb = W2[(kk + 1) * 64 + n];
        float ha, la, hb, lb;
        bsplit(wa, ha, la); bsplit(wb, hb, lb);
        g_W2ph[i] = pkbf(ha, hb);
        g_W2pl[i] = pkbf(la, lb);
    }
}

// ---------------- K: decode edges + node histogram (block-local detect) -----
__global__ void k_edges(const void* __restrict__ ei_raw, int E, int Nn) {
    __shared__ int s_nz;
    int t = threadIdx.x;               // 256
    if (t == 0) s_nz = 0;
    __syncthreads();
    const int* ei32 = (const int*)ei_raw;
    if (ei32[2 * t + 1]) atomicOr(&s_nz, 1);
    __syncthreads();
    bool e64 = (s_nz == 0);
    int e = blockIdx.x * blockDim.x + t;
    if (e >= E) return;
    int ci, ri;
    if (e64) {
        ci = (int)((const long long*)ei_raw)[e];
        ri = (int)((const long long*)ei_raw)[(size_t)E + e];
    } else {
        ci = ei32[e];
        ri = ei32[E + e];
    }
    ci = min(max(ci, 0), Nn - 1);
    ri = min(max(ri, 0), Nn - 1);
    g_col[e] = ci; g_row[e] = ri;
    atomicAdd(&g_nodeCnt[ci], 1);
}

// ---------------- K: tile-scan (self-clearing) + graph offsets + bt detect ---
__global__ void k_scan_node(const void* __restrict__ bt_raw, int E, int Nn) {
    __shared__ int warpSum[32];
    __shared__ int s_bt, s_carry;
    int t = threadIdx.x;               // 1024
    int lane = t & 31, w = t >> 5;
    if (t == 0) { s_bt = 0; s_carry = 0; }
    __syncthreads();
    {
        const int* bt32 = (const int*)bt_raw;
        int lim = Nn / 2 < 16384 ? Nn / 2 : 16384;
        int nz = 0;
        for (int i = t; i < lim; i += 1024) nz |= bt32[2 * i + 1];
        for (int d = 16; d; d >>= 1) nz |= __shfl_xor_sync(~0u, nz, d);
        if (lane == 0 && nz) atomicOr(&s_bt, 1);
    }
    __syncthreads();
    bool b64 = (s_bt == 0);
    if (t == 0) g_is64_bt = b64 ? 1 : 0;

    int ntile = (Nn + 4095) >> 12;
    for (int tile = 0; tile < ntile; tile++) {
        int idx0 = (tile << 12) + t * 4;
        int c0 = 0, c1 = 0, c2 = 0, c3 = 0;
        if (idx0 + 3 < Nn) {
            int4 c = *(const int4*)&g_nodeCnt[idx0];
            c0 = c.x; c1 = c.y; c2 = c.z; c3 = c.w;
            int4 z = make_int4(0, 0, 0, 0);
            *(int4*)&g_nodeCnt[idx0] = z;            // self-clear for next replay
        } else {
            if (idx0 + 0 < Nn) { c0 = g_nodeCnt[idx0 + 0]; g_nodeCnt[idx0 + 0] = 0; }
            if (idx0 + 1 < Nn) { c1 = g_nodeCnt[idx0 + 1]; g_nodeCnt[idx0 + 1] = 0; }
            if (idx0 + 2 < Nn) { c2 = g_nodeCnt[idx0 + 2]; g_nodeCnt[idx0 + 2] = 0; }
            if (idx0 + 3 < Nn) { c3 = g_nodeCnt[idx0 + 3]; g_nodeCnt[idx0 + 3] = 0; }
        }
        int s = c0 + c1 + c2 + c3;
        int v = s;
        for (int d = 1; d < 32; d <<= 1) {
            int u = __shfl_up_sync(~0u, v, d);
            if (lane >= d) v += u;
        }
        if (lane == 31) warpSum[w] = v;
        __syncthreads();
        if (w == 0) {
            int x = warpSum[lane];
            for (int d = 1; d < 32; d <<= 1) {
                int u = __shfl_up_sync(~0u, x, d);
                if (lane >= d) x += u;
            }
            warpSum[lane] = x;
        }
        __syncthreads();
        int warpExcl = w ? warpSum[w - 1] : 0;
        int run = s_carry + warpExcl + (v - s);
        if (idx0 + 0 < Nn) { g_nodeOff[idx0 + 0] = run; g_cursorN[idx0 + 0] = run; run += c0; }
        if (idx0 + 1 < Nn) { g_nodeOff[idx0 + 1] = run; g_cursorN[idx0 + 1] = run; run += c1; }
        if (idx0 + 2 < Nn) { g_nodeOff[idx0 + 2] = run; g_cursorN[idx0 + 2] = run; run += c2; }
        if (idx0 + 3 < Nn) { g_nodeOff[idx0 + 3] = run; g_cursorN[idx0 + 3] = run; run += c3; }
        __syncthreads();
        if (t == 0) s_carry += warpSum[31];
        __syncthreads();
    }
    if (t < NGRAPH) {
        int lo = 0, hi = Nn;
        while (lo < hi) {
            int mid = (lo + hi) >> 1;
            long long bv = b64 ? ((const long long*)bt_raw)[mid]
                               : (long long)((const int*)bt_raw)[mid];
            if (bv < (long long)t) lo = mid + 1; else hi = mid;
        }
        g_off[t] = (lo < Nn) ? g_nodeOff[lo] : E;
    }
    if (t == 0) g_off[NGRAPH] = E;
}

// ---------------- K4: P/Q = emb @ W1-half  (FFMA2) ---------------------------
__global__ void k_pq(const float* __restrict__ emb,
                     const float* __restrict__ W1, int Nn) {
    __shared__ __align__(16) float Xs[128 * 34];
    __shared__ __align__(16) float Ws[32 * 64];
    int tid = threadIdx.x;
    int m0  = blockIdx.x * 128;
    int nb  = blockIdx.y * 64;
    int z   = blockIdx.z;
    int r16 = tid >> 3;
    int cb  = (tid & 7) * 8;

    unsigned long long acc[8][4];
#pragma unroll
    for (int i = 0; i < 8; i++)
#pragma unroll
        for (int j = 0; j < 4; j++) acc[i][j] = 0ULL;

    for (int kc = 0; kc < 2; kc++) {
#pragma unroll
        for (int t = tid; t < 128 * 8; t += 128) {
            int rr = t >> 3, q = t & 7;
            int node = m0 + rr; if (node >= Nn) node = Nn - 1;
            float4 v = *(const float4*)&emb[node * 64 + kc * 32 + q * 4];
            float* d = &Xs[rr * 34 + q * 4];
            *(float2*)&d[0] = make_float2(v.x, v.y);
            *(float2*)&d[2] = make_float2(v.z, v.w);
        }
#pragma unroll
        for (int t = tid; t < 512; t += 128) {
            int k = t >> 4, q = t & 15;
            *(float4*)&Ws[k * 64 + q * 4] =
                *(const float4*)&W1[(z * 64 + kc * 32 + k) * 256 + nb + q * 4];
        }
        __syncthreads();
#pragma unroll
        for (int k = 0; k < 32; k++) {
            ulonglong2 bA = *(const ulonglong2*)&Ws[k * 64 + cb + 0];
            ulonglong2 bB = *(const ulonglong2*)&Ws[k * 64 + cb + 4];
#pragma unroll
            for (int i = 0; i < 8; i++) {
                unsigned long long pa = pack2(Xs[(r16 + 16 * i) * 34 + k]);
                acc[i][0] = ffma2(pa, bA.x, acc[i][0]);
                acc[i][1] = ffma2(pa, bA.y, acc[i][1]);
                acc[i][2] = ffma2(pa, bB.x, acc[i][2]);
                acc[i][3] = ffma2(pa, bB.y, acc[i][3]);
            }
        }
        __syncthreads();
    }
    float* dst = z ? g_Q : g_P;
#pragma unroll
    for (int i = 0; i < 8; i++) {
        int node = m0 + r16 + 16 * i;
        if (node < Nn) {
            float* o = &dst[node * 256 + nb + cb];
            *(unsigned long long*)&o[0] = acc[i][0];
            *(unsigned long long*)&o[2] = acc[i][1];
            *(unsigned long long*)&o[4] = acc[i][2];
            *(unsigned long long*)&o[6] = acc[i][3];
        }
    }
}

// ---------------- K: scatter edges into col-sorted order ---------------------
__global__ void k_scatter(const void* __restrict__ bt_raw, int E) {
    int e = blockIdx.x * blockDim.x + threadIdx.x;
    if (e >= E) return;
    int ci = g_col[e];
    int pos = atomicAdd(&g_cursorN[ci], 1);
    bool b64 = (g_is64_bt != 0);
    int sg = b64 ? (int)((const long long*)bt_raw)[ci]
                 : ((const int*)bt_raw)[ci];
    sg = min(max(sg, 0), NGRAPH - 1);
    g_perm[pos] = e;
    g_colS[pos] = ci;
    g_rowS[pos] = g_row[e];
    g_segS[pos] = sg;
}

// ---------------- K: per-(graph, 32-channel) stats of h1 = P[c]+Q[r] ---------
__global__ void k_stats1() {
    int g  = blockIdx.x;
    int c0 = blockIdx.y * 32;
    int lane = threadIdx.x & 31, w = threadIdx.x >> 5;   // 8 warps
    int start = g_off[g], end = g_off[g + 1];
    int ch = c0 + lane;
    float s1 = 0.f, s2 = 0.f;
    int m = start + w;
    for (; m + 8 < end; m += 16) {
        float va = g_P[g_colS[m] * 256 + ch] + g_Q[g_rowS[m] * 256 + ch];
        float vb = g_P[g_colS[m + 8] * 256 + ch] + g_Q[g_rowS[m + 8] * 256 + ch];
        s1 += va + vb; s2 += va * va + vb * vb;
    }
    if (m < end) {
        float v = g_P[g_colS[m] * 256 + ch] + g_Q[g_rowS[m] * 256 + ch];
        s1 += v; s2 += v * v;
    }
    __shared__ float a1[8][32], a2[8][32];
    a1[w][lane] = s1; a2[w][lane] = s2;
    __syncthreads();
    if (w == 0) {
#pragma unroll
        for (int t = 1; t < 8; t++) { s1 += a1[t][lane]; s2 += a2[t][lane]; }
        int cnti = end - start; if (cnti < 1) cnti = 1;
        float cnt  = (float)cnti;
        float mean = s1 / cnt;
        float var  = fmaxf(s2 / cnt - mean * mean, 0.f);
        g_mean1[g * 256 + ch] = mean;
        g_rstd1[g * 256 + ch] = rsqrtf(var + EPS);
    }
}

// ---------------- K: h2 via cp.async-pipelined bf16 3-term MMA ---------------
// Dynamic smem: rawP[2][128][32]f, rawQ[2][128][32]f, Ah/Al[128*20]u32,
// Bh/Bl[64*20]u32, cS/rS/sS[128]i  -> 97792 B.
#define GM2_SMEM 97792

__global__ void __launch_bounds__(256) k_gemm2(int E) {
    extern __shared__ char dsm[];
    float*    rawP = (float*)dsm;                 // 2*4096
    float*    rawQ = rawP + 8192;                  // 2*4096
    uint32_t* Ah   = (uint32_t*)(rawQ + 8192);     // 2560
    uint32_t* Al   = Ah + 2560;
    uint32_t* Bh   = Al + 2560;                    // 1280
    uint32_t* Bl   = Bh + 1280;
    int*      cS   = (int*)(Bl + 1280);
    int*      rS   = cS + 128;
    int*      sS   = rS + 128;

    int tid = threadIdx.x;
    int m0  = blockIdx.x * 128;
    int w = tid >> 5, lane = tid & 31, gq = lane >> 2, tig = lane & 3;

    if (tid < 128) {
        int m = m0 + tid; if (m >= E) m = E - 1;
        cS[tid] = g_colS[m]; rS[tid] = g_rowS[m]; sS[tid] = g_segS[m];
    }
    __syncthreads();

    float acc[8][4];
#pragma unroll
    for (int i = 0; i < 8; i++)
#pragma unroll
        for (int j = 0; j < 4; j++) acc[i][j] = 0.f;

    int rA   = tid >> 1;
    int half = tid & 1;
    int sgA  = sS[rA];

    // issue gather for chunk 0
    {
#pragma unroll
        for (int i = 0; i < 4; i++) {
            int lin = tid + i * 256;
            int rr = lin >> 3, q = lin & 7;
            cpasync16(&rawP[rr * 32 + q * 4], &g_P[(size_t)cS[rr] * 256 + q * 4]);
            cpasync16(&rawQ[rr * 32 + q * 4], &g_Q[(size_t)rS[rr] * 256 + q * 4]);
        }
        asm volatile("cp.async.commit_group;" ::: "memory");
    }

    for (int kc = 0; kc < 8; kc++) {
        int buf = kc & 1;
        if (kc < 7) {
            int nb = (buf ^ 1) * 4096;
            int ko = (kc + 1) * 32;
#pragma unroll
            for (int i = 0; i < 4; i++) {
                int lin = tid + i * 256;
                int rr = lin >> 3, q = lin & 7;
                cpasync16(&rawP[nb + rr * 32 + q * 4],
                          &g_P[(size_t)cS[rr] * 256 + ko + q * 4]);
                cpasync16(&rawQ[nb + rr * 32 + q * 4],
                          &g_Q[(size_t)rS[rr] * 256 + ko + q * 4]);
            }
            asm volatile("cp.async.commit_group;" ::: "memory");
            asm volatile("cp.async.wait_group 1;" ::: "memory");
        } else {
            asm volatile("cp.async.wait_group 0;" ::: "memory");
        }
        __syncthreads();
        // ---- stage A: normalize + relu + bf16 split from raw smem -----------
        {
            const float* rp  = &rawP[buf * 4096 + rA * 32 + half * 16];
            const float* rq  = &rawQ[buf * 4096 + rA * 32 + half * 16];
            const float* muB = &g_mean1[sgA * 256 + kc * 32 + half * 16];
            const float* rsB = &g_rstd1[sgA * 256 + kc * 32 + half * 16];
#pragma unroll
            for (int q = 0; q < 4; q++) {
                float4 p  = *(const float4*)(rp + q * 4);
                float4 qv = *(const float4*)(rq + q * 4);
                float4 mu = *(const float4*)(muB + q * 4);
                float4 rs = *(const float4*)(rsB + q * 4);
                float v0 = fmaxf((p.x + qv.x - mu.x) * rs.x, 0.f);
                float v1 = fmaxf((p.y + qv.y - mu.y) * rs.y, 0.f);
                float v2 = fmaxf((p.z + qv.z - mu.z) * rs.z, 0.f);
                float v3 = fmaxf((p.w + qv.w - mu.w) * rs.w, 0.f);
                float h0, l0, h1, l1, h2, l2, h3, l3;
                bsplit(v0, h0, l0); bsplit(v1, h1, l1);
                bsplit(v2, h2, l2); bsplit(v3, h3, l3);
                int o = rA * 20 + half * 8 + q * 2;
                Ah[o]     = pkbf(h0, h1);
                Ah[o + 1] = pkbf(h2, h3);
                Al[o]     = pkbf(l0, l1);
                Al[o + 1] = pkbf(l2, l3);
            }
        }
        // ---- stage B: copy pre-split W2 chunk --------------------------------
#pragma unroll
        for (int i = tid; i < 1024; i += 256) {
            int n = i >> 4, k2 = i & 15;
            Bh[n * 20 + k2] = g_W2ph[kc * 1024 + i];
            Bl[n * 20 + k2] = g_W2pl[kc * 1024 + i];
        }
        __syncthreads();
        // ---- MMA --------------------------------------------------------------
        int r0 = w * 16;
#pragma unroll
        for (int ks = 0; ks < 2; ks++) {
            int kb = ks * 8;
            uint32_t ah0 = Ah[(r0 + gq) * 20 + kb + tig];
            uint32_t ah1 = Ah[(r0 + gq + 8) * 20 + kb + tig];
            uint32_t ah2 = Ah[(r0 + gq) * 20 + kb + tig + 4];
            uint32_t ah3 = Ah[(r0 + gq + 8) * 20 + kb + tig + 4];
            uint32_t al0 = Al[(r0 + gq) * 20 + kb + tig];
            uint32_t al1 = Al[(r0 + gq + 8) * 20 + kb + tig];
            uint32_t al2 = Al[(r0 + gq) * 20 + kb + tig + 4];
            uint32_t al3 = Al[(r0 + gq + 8) * 20 + kb + tig + 4];
#pragma unroll
            for (int nt = 0; nt < 8; nt++) {
                int nrow = nt * 8 + gq;
                uint32_t bh0 = Bh[nrow * 20 + kb + tig];
                uint32_t bh1 = Bh[nrow * 20 + kb + tig + 4];
                uint32_t bl0 = Bl[nrow * 20 + kb + tig];
                uint32_t bl1 = Bl[nrow * 20 + kb + tig + 4];
                mma16816(acc[nt], ah0, ah1, ah2, ah3, bh0, bh1);
                mma16816(acc[nt], ah0, ah1, ah2, ah3, bl0, bl1);
                mma16816(acc[nt], al0, al1, al2, al3, bh0, bh1);
            }
        }
        // no sync needed here: next iteration's stage is fenced by the
        // wait_group + __syncthreads at loop top.
    }
    // ---- epilogue --------------------------------------------------------------
    int row0 = m0 + w * 16 + gq;
    int row1 = row0 + 8;
#pragma unroll
    for (int nt = 0; nt < 8; nt++) {
        int cidx = nt * 8 + tig * 2;
        if (row0 < E)
            *(float2*)&g_h2[(size_t)row0 * 64 + cidx] = make_float2(acc[nt][0], acc[nt][1]);
        if (row1 < E)
            *(float2*)&g_h2[(size_t)row1 * 64 + cidx] = make_float2(acc[nt][2], acc[nt][3]);
    }
}

// ---------------- K: stats of h2 ----------------------------------------------
__global__ void k_stats2() {
    int g  = blockIdx.x;
    int c0 = blockIdx.y * 32;
    int lane = threadIdx.x & 31, w = threadIdx.x >> 5;
    int start = g_off[g], end = g_off[g + 1];
    int ch = c0 + lane;
    float s1 = 0.f, s2 = 0.f;
    int m = start + w;
    for (; m + 8 < end; m += 16) {
        float va = g_h2[(size_t)m * 64 + ch];
        float vb = g_h2[(size_t)(m + 8) * 64 + ch];
        s1 += va + vb; s2 += va * va + vb * vb;
    }
    if (m < end) {
        float v = g_h2[(size_t)m * 64 + ch];
        s1 += v; s2 += v * v;
    }
    __shared__ float a1[8][32], a2[8][32];
    a1[w][lane] = s1; a2[w][lane] = s2;
    __syncthreads();
    if (w == 0) {
#pragma unroll
        for (int t = 1; t < 8; t++) { s1 += a1[t][lane]; s2 += a2[t][lane]; }
        int cnti = end - start; if (cnti < 1) cnti = 1;
        float cnt  = (float)cnti;
        float mean = s1 / cnt;
        float var  = fmaxf(s2 / cnt - mean * mean, 0.f);
        g_mean2[g * 64 + ch] = mean;
        g_rstd2[g * 64 + ch] = rsqrtf(var + EPS);
    }
}

// ---------------- K: out[perm[m]] = relu(norm2(h2)) . W3 + b3 ----------------
__global__ void k_final(const float* __restrict__ W3,
                        const float* __restrict__ b3,
                        float* __restrict__ out, int E) {
    __shared__ __align__(16) float sm[128 * 65];
    __shared__ float w3s[64];
    __shared__ int   sS[128];
    int tid = threadIdx.x;   // 128
    int m0  = blockIdx.x * 128;
    if (tid < 64) w3s[tid] = W3[tid];
    {
        int m = m0 + tid; if (m >= E) m = E - 1;
        sS[tid] = g_segS[m];
    }
    __syncthreads();
#pragma unroll
    for (int t = tid; t < 128 * 16; t += 128) {
        int rr = t >> 4, q = t & 15;
        int m = m0 + rr; if (m >= E) m = E - 1;
        float4 v  = *(const float4*)&g_h2[(size_t)m * 64 + q * 4];
        int s = sS[rr];
        float4 mu = *(const float4*)&g_mean2[s * 64 + q * 4];
        float4 rs = *(const float4*)&g_rstd2[s * 64 + q * 4];
        float* d = &sm[rr * 65 + q * 4];
        d[0] = fmaxf((v.x - mu.x) * rs.x, 0.f);
        d[1] = fmaxf((v.y - mu.y) * rs.y, 0.f);
        d[2] = fmaxf((v.z - mu.z) * rs.z, 0.f);
        d[3] = fmaxf((v.w - mu.w) * rs.w, 0.f);
    }
    __syncthreads();
    int m = m0 + tid;
    if (m < E) {
        float acc = 0.f;
#pragma unroll
        for (int k = 0; k < 64; k++) acc += sm[tid * 65 + k] * w3s[k];
        out[g_perm[m]] = acc + b3[0];
    }
}

// ---------------- launch -------------------------------------------------------
extern "C" void kernel_launch(void* const* d_in, const int* in_sizes, int n_in,
                              void* d_out, int out_size) {
    const float* emb = (const float*)d_in[0];
    const void*  ei  = d_in[1];
    const void*  bt  = d_in[2];
    const float* W1  = (const float*)d_in[3];
    // d_in[4] = b1 : cancels exactly through affine-free InstanceNorm
    const float* W2  = (const float*)d_in[5];
    // d_in[6] = b2 : cancels exactly through affine-free InstanceNorm
    const float* W3  = (const float*)d_in[7];
    const float* b3  = (const float*)d_in[8];
    float* out = (float*)d_out;

    int Nn = in_sizes[0] / 64;
    int E  = in_sizes[1] / 2;

    cudaFuncSetAttribute(k_gemm2, cudaFuncAttributeMaxDynamicSharedMemorySize,
                         GM2_SMEM);

    dim3 gPQ((Nn + 127) / 128, 4, 2);
    k_pq<<<gPQ, 128>>>(emb, W1, Nn);                             // 1
    k_edges<<<(E + 255) / 256, 256>>>(ei, E, Nn);                // 2
    k_scan_node<<<1, 1024>>>(bt, E, Nn);                         // 3 (self-clearing)
    k_scatter<<<(E + 255) / 256, 256>>>(bt, E);                  // 4 (profiled)
    k_w2cvt<<<32, 256>>>(W2);                                    // 5
    k_stats1<<<dim3(128, 8), 256>>>();                           // 6
    k_gemm2<<<(E + 127) / 128, 256, GM2_SMEM>>>(E);              // 7
    k_stats2<<<dim3(128, 2), 256>>>();                           // 8
    k_final<<<(E + 127) / 128, 128>>>(W3, b3, out, E);           // 9
}

// round 7
// speedup vs baseline: 1.2019x; 1.2019x over previous
#include <cuda_runtime.h>
#include <cuda_bf16.h>
#include <cstdint>

#define EPS 1e-5f
#define NGRAPH 128
#define EMAX 800000
#define NMAX 50000

// ---------------- scratch (__device__ globals; no allocation allowed) -------
__device__ int g_is64_bt;
__device__ int g_nodeCnt[NMAX];
__device__ int g_nodeOff[NMAX];
__device__ int g_cursorN[NMAX];
__device__ int g_off[NGRAPH + 1];
__device__ int g_col[EMAX];
__device__ int g_row[EMAX];
__device__ int g_perm[EMAX];
__device__ int g_segS[EMAX];
__device__ int g_colS[EMAX];
__device__ int g_rowS[EMAX];
__device__ __align__(16) float g_P[NMAX * 256];   // emb @ W1[:64 ,:]
__device__ __align__(16) float g_Q[NMAX * 256];   // emb @ W1[64:,:]
__device__ __align__(16) float g_h2[(size_t)EMAX * 64];
__device__ __align__(16) float g_mean1[NGRAPH * 256];
__device__ __align__(16) float g_rstd1[NGRAPH * 256];
__device__ __align__(16) float g_mean2[NGRAPH * 64];
__device__ __align__(16) float g_rstd2[NGRAPH * 64];
// W2 pre-split bf16 hi/lo packed b32: [kc 8][n 64][k2 16]
__device__ __align__(16) uint32_t g_W2ph[8192];
__device__ __align__(16) uint32_t g_W2pl[8192];
// W1 pre-split bf16 hi/lo packed b32: [z 2][nb 4][kc 2][n 64][k2 16]
__device__ __align__(16) uint32_t g_W1ph[16384];
__device__ __align__(16) uint32_t g_W1pl[16384];

// ---------------- helpers ----------------------------------------------------
__device__ __forceinline__ uint32_t pkbf(float a, float b) {
    __nv_bfloat162 h = __floats2bfloat162_rn(a, b);
    return *(uint32_t*)&h;
}
__device__ __forceinline__ void bsplit(float v, float& hi, float& lo) {
    __nv_bfloat16 h = __float2bfloat16(v);
    hi = __bfloat162float(h);
    lo = v - hi;
}
__device__ __forceinline__ void mma16816(float* c, uint32_t a0, uint32_t a1,
                                         uint32_t a2, uint32_t a3,
                                         uint32_t b0, uint32_t b1) {
    asm volatile(
        "mma.sync.aligned.m16n8k16.row.col.f32.bf16.bf16.f32 "
        "{%0,%1,%2,%3}, {%4,%5,%6,%7}, {%8,%9}, {%0,%1,%2,%3};"
        : "+f"(c[0]), "+f"(c[1]), "+f"(c[2]), "+f"(c[3])
        : "r"(a0), "r"(a1), "r"(a2), "r"(a3), "r"(b0), "r"(b1));
}

// ---------------- K: W1+W2 bf16 hi/lo pre-split --------------------------------
__global__ void k_wcvt(const float* __restrict__ W1,
                       const float* __restrict__ W2) {
    int i = blockIdx.x * 256 + threadIdx.x;   // 24576 total
    if (i < 16384) {
        // W1: [z 2][nb 4][kc 2][n 64][k2 16]
        int z  = i >> 13;
        int nb = (i >> 11) & 3;
        int kc = (i >> 10) & 1;
        int n  = (i >> 4) & 63;
        int k2 = i & 15;
        int kk  = z * 64 + kc * 32 + k2 * 2;    // W1 row
        int col = nb * 64 + n;                   // W1 col
        float wa = W1[kk * 256 + col];
        float wb = W1[(kk + 1) * 256 + col];
        float ha, la, hb, lb;
        bsplit(wa, ha, la); bsplit(wb, hb, lb);
        g_W1ph[i] = pkbf(ha, hb);
        g_W1pl[i] = pkbf(la, lb);
    } else if (i < 24576) {
        int j = i - 16384;
        int kc = j >> 10, n = (j >> 4) & 63, k2 = j & 15;
        int kk = kc * 32 + k2 * 2;
        float wa = W2[kk * 64 + n];
        float wb = W2[(kk + 1) * 64 + n];
        float ha, la, hb, lb;
        bsplit(wa, ha, la); bsplit(wb, hb, lb);
        g_W2ph[j] = pkbf(ha, hb);
        g_W2pl[j] = pkbf(la, lb);
    }
}

// ---------------- K: decode edges + node histogram (block-local detect) -----
__global__ void k_edges(const void* __restrict__ ei_raw, int E, int Nn) {
    __shared__ int s_nz;
    int t = threadIdx.x;               // 256
    if (t == 0) s_nz = 0;
    __syncthreads();
    const int* ei32 = (const int*)ei_raw;
    if (ei32[2 * t + 1]) atomicOr(&s_nz, 1);
    __syncthreads();
    bool e64 = (s_nz == 0);
    int e = blockIdx.x * blockDim.x + t;
    if (e >= E) return;
    int ci, ri;
    if (e64) {
        ci = (int)((const long long*)ei_raw)[e];
        ri = (int)((const long long*)ei_raw)[(size_t)E + e];
    } else {
        ci = ei32[e];
        ri = ei32[E + e];
    }
    ci = min(max(ci, 0), Nn - 1);
    ri = min(max(ri, 0), Nn - 1);
    g_col[e] = ci; g_row[e] = ri;
    atomicAdd(&g_nodeCnt[ci], 1);
}

// ---------------- K: tile-scan (self-clearing) + graph offsets + bt detect ---
__global__ void k_scan_node(const void* __restrict__ bt_raw, int E, int Nn) {
    __shared__ int warpSum[32];
    __shared__ int s_bt, s_carry;
    int t = threadIdx.x;               // 1024
    int lane = t & 31, w = t >> 5;
    if (t == 0) { s_bt = 0; s_carry = 0; }
    __syncthreads();
    {
        const int* bt32 = (const int*)bt_raw;
        int lim = Nn / 2 < 16384 ? Nn / 2 : 16384;
        int nz = 0;
        for (int i = t; i < lim; i += 1024) nz |= bt32[2 * i + 1];
        for (int d = 16; d; d >>= 1) nz |= __shfl_xor_sync(~0u, nz, d);
        if (lane == 0 && nz) atomicOr(&s_bt, 1);
    }
    __syncthreads();
    bool b64 = (s_bt == 0);
    if (t == 0) g_is64_bt = b64 ? 1 : 0;

    int ntile = (Nn + 4095) >> 12;
    for (int tile = 0; tile < ntile; tile++) {
        int idx0 = (tile << 12) + t * 4;
        int c0 = 0, c1 = 0, c2 = 0, c3 = 0;
        if (idx0 + 3 < Nn) {
            int4 c = *(const int4*)&g_nodeCnt[idx0];
            c0 = c.x; c1 = c.y; c2 = c.z; c3 = c.w;
            int4 z = make_int4(0, 0, 0, 0);
            *(int4*)&g_nodeCnt[idx0] = z;            // self-clear for next replay
        } else {
            if (idx0 + 0 < Nn) { c0 = g_nodeCnt[idx0 + 0]; g_nodeCnt[idx0 + 0] = 0; }
            if (idx0 + 1 < Nn) { c1 = g_nodeCnt[idx0 + 1]; g_nodeCnt[idx0 + 1] = 0; }
            if (idx0 + 2 < Nn) { c2 = g_nodeCnt[idx0 + 2]; g_nodeCnt[idx0 + 2] = 0; }
            if (idx0 + 3 < Nn) { c3 = g_nodeCnt[idx0 + 3]; g_nodeCnt[idx0 + 3] = 0; }
        }
        int s = c0 + c1 + c2 + c3;
        int v = s;
        for (int d = 1; d < 32; d <<= 1) {
            int u = __shfl_up_sync(~0u, v, d);
            if (lane >= d) v += u;
        }
        if (lane == 31) warpSum[w] = v;
        __syncthreads();
        if (w == 0) {
            int x = warpSum[lane];
            for (int d = 1; d < 32; d <<= 1) {
                int u = __shfl_up_sync(~0u, x, d);
                if (lane >= d) x += u;
            }
            warpSum[lane] = x;
        }
        __syncthreads();
        int warpExcl = w ? warpSum[w - 1] : 0;
        int run = s_carry + warpExcl + (v - s);
        if (idx0 + 0 < Nn) { g_nodeOff[idx0 + 0] = run; g_cursorN[idx0 + 0] = run; run += c0; }
        if (idx0 + 1 < Nn) { g_nodeOff[idx0 + 1] = run; g_cursorN[idx0 + 1] = run; run += c1; }
        if (idx0 + 2 < Nn) { g_nodeOff[idx0 + 2] = run; g_cursorN[idx0 + 2] = run; run += c2; }
        if (idx0 + 3 < Nn) { g_nodeOff[idx0 + 3] = run; g_cursorN[idx0 + 3] = run; run += c3; }
        __syncthreads();
        if (t == 0) s_carry += warpSum[31];
        __syncthreads();
    }
    if (t < NGRAPH) {
        int lo = 0, hi = Nn;
        while (lo < hi) {
            int mid = (lo + hi) >> 1;
            long long bv = b64 ? ((const long long*)bt_raw)[mid]
                               : (long long)((const int*)bt_raw)[mid];
            if (bv < (long long)t) lo = mid + 1; else hi = mid;
        }
        g_off[t] = (lo < Nn) ? g_nodeOff[lo] : E;
    }
    if (t == 0) g_off[NGRAPH] = E;
}

// ---------------- K: P/Q = emb @ W1-half via 3-term bf16 MMA ------------------
// Block: 256 threads, M=128 nodes, N=64 (blockIdx.y), z=P/Q (blockIdx.z), K=64.
__global__ void __launch_bounds__(256) k_pqm(const float* __restrict__ emb, int Nn) {
    __shared__ uint32_t Ah[128 * 20];
    __shared__ uint32_t Al[128 * 20];
    __shared__ uint32_t Bh[64 * 20];
    __shared__ uint32_t Bl[64 * 20];
    int tid = threadIdx.x;
    int m0  = blockIdx.x * 128;
    int nb  = blockIdx.y;
    int z   = blockIdx.z;
    int w = tid >> 5, lane = tid & 31, gq = lane >> 2, tig = lane & 3;

    float acc[8][4];
#pragma unroll
    for (int i = 0; i < 8; i++)
#pragma unroll
        for (int j = 0; j < 4; j++) acc[i][j] = 0.f;

    int rA   = tid >> 1;
    int half = tid & 1;
    int node = min(m0 + rA, Nn - 1);
    const uint32_t* w1h = &g_W1ph[(size_t)((z * 4 + nb) * 2) * 1024];
    const uint32_t* w1l = &g_W1pl[(size_t)((z * 4 + nb) * 2) * 1024];

    for (int kc = 0; kc < 2; kc++) {
        // ---- stage A: emb chunk -> bf16 hi/lo ---------------------------------
        {
            const float* er = &emb[(size_t)node * 64 + kc * 32 + half * 16];
#pragma unroll
            for (int q = 0; q < 4; q++) {
                float4 v = *(const float4*)(er + q * 4);
                float h0, l0, h1, l1, h2, l2, h3, l3;
                bsplit(v.x, h0, l0); bsplit(v.y, h1, l1);
                bsplit(v.z, h2, l2); bsplit(v.w, h3, l3);
                int o = rA * 20 + half * 8 + q * 2;
                Ah[o]     = pkbf(h0, h1);
                Ah[o + 1] = pkbf(h2, h3);
                Al[o]     = pkbf(l0, l1);
                Al[o + 1] = pkbf(l2, l3);
            }
        }
        // ---- stage B: copy pre-split W1 chunk ---------------------------------
#pragma unroll
        for (int i = tid; i < 1024; i += 256) {
            int n = i >> 4, k2 = i & 15;
            Bh[n * 20 + k2] = w1h[kc * 1024 + i];
            Bl[n * 20 + k2] = w1l[kc * 1024 + i];
        }
        __syncthreads();
        // ---- MMA ----------------------------------------------------------------
        int r0 = w * 16;
#pragma unroll
        for (int ks = 0; ks < 2; ks++) {
            int kb = ks * 8;
            uint32_t ah0 = Ah[(r0 + gq) * 20 + kb + tig];
            uint32_t ah1 = Ah[(r0 + gq + 8) * 20 + kb + tig];
            uint32_t ah2 = Ah[(r0 + gq) * 20 + kb + tig + 4];
            uint32_t ah3 = Ah[(r0 + gq + 8) * 20 + kb + tig + 4];
            uint32_t al0 = Al[(r0 + gq) * 20 + kb + tig];
            uint32_t al1 = Al[(r0 + gq + 8) * 20 + kb + tig];
            uint32_t al2 = Al[(r0 + gq) * 20 + kb + tig + 4];
            uint32_t al3 = Al[(r0 + gq + 8) * 20 + kb + tig + 4];
#pragma unroll
            for (int nt = 0; nt < 8; nt++) {
                int nrow = nt * 8 + gq;
                uint32_t bh0 = Bh[nrow * 20 + kb + tig];
                uint32_t bh1 = Bh[nrow * 20 + kb + tig + 4];
                uint32_t bl0 = Bl[nrow * 20 + kb + tig];
                uint32_t bl1 = Bl[nrow * 20 + kb + tig + 4];
                mma16816(acc[nt], ah0, ah1, ah2, ah3, bh0, bh1);
                mma16816(acc[nt], ah0, ah1, ah2, ah3, bl0, bl1);
                mma16816(acc[nt], al0, al1, al2, al3, bh0, bh1);
            }
        }
        __syncthreads();
    }
    // ---- epilogue --------------------------------------------------------------
    float* dst = z ? g_Q : g_P;
    int row0 = m0 + w * 16 + gq;
    int row1 = row0 + 8;
#pragma unroll
    for (int nt = 0; nt < 8; nt++) {
        int cidx = nb * 64 + nt * 8 + tig * 2;
        if (row0 < Nn)
            *(float2*)&dst[(size_t)row0 * 256 + cidx] = make_float2(acc[nt][0], acc[nt][1]);
        if (row1 < Nn)
            *(float2*)&dst[(size_t)row1 * 256 + cidx] = make_float2(acc[nt][2], acc[nt][3]);
    }
}

// ---------------- K: scatter edges into col-sorted order ---------------------
__global__ void k_scatter(const void* __restrict__ bt_raw, int E) {
    int e = blockIdx.x * blockDim.x + threadIdx.x;
    if (e >= E) return;
    int ci = g_col[e];
    int pos = atomicAdd(&g_cursorN[ci], 1);
    bool b64 = (g_is64_bt != 0);
    int sg = b64 ? (int)((const long long*)bt_raw)[ci]
                 : ((const int*)bt_raw)[ci];
    sg = min(max(sg, 0), NGRAPH - 1);
    g_perm[pos] = e;
    g_colS[pos] = ci;
    g_rowS[pos] = g_row[e];
    g_segS[pos] = sg;
}

// ---------------- K: per-(graph, 32-channel) stats of h1 = P[c]+Q[r] ---------
__global__ void k_stats1() {
    int g  = blockIdx.x;
    int c0 = blockIdx.y * 32;
    int lane = threadIdx.x & 31, w = threadIdx.x >> 5;   // 8 warps
    int start = g_off[g], end = g_off[g + 1];
    int ch = c0 + lane;
    float s1 = 0.f, s2 = 0.f;
    int m = start + w;
    for (; m + 8 < end; m += 16) {
        float va = g_P[g_colS[m] * 256 + ch] + g_Q[g_rowS[m] * 256 + ch];
        float vb = g_P[g_colS[m + 8] * 256 + ch] + g_Q[g_rowS[m + 8] * 256 + ch];
        s1 += va + vb; s2 += va * va + vb * vb;
    }
    if (m < end) {
        float v = g_P[g_colS[m] * 256 + ch] + g_Q[g_rowS[m] * 256 + ch];
        s1 += v; s2 += v * v;
    }
    __shared__ float a1[8][32], a2[8][32];
    a1[w][lane] = s1; a2[w][lane] = s2;
    __syncthreads();
    if (w == 0) {
#pragma unroll
        for (int t = 1; t < 8; t++) { s1 += a1[t][lane]; s2 += a2[t][lane]; }
        int cnti = end - start; if (cnti < 1) cnti = 1;
        float cnt  = (float)cnti;
        float mean = s1 / cnt;
        float var  = fmaxf(s2 / cnt - mean * mean, 0.f);
        g_mean1[g * 256 + ch] = mean;
        g_rstd1[g * 256 + ch] = rsqrtf(var + EPS);
    }
}

// ---------------- K: h2 via direct-load bf16 3-term MMA (round-5 structure) --
__global__ void __launch_bounds__(256) k_gemm2(int E) {
    __shared__ uint32_t Ah[128 * 20];
    __shared__ uint32_t Al[128 * 20];
    __shared__ uint32_t Bh[64 * 20];
    __shared__ uint32_t Bl[64 * 20];
    __shared__ int cS[128], rS[128], sS[128];
    int tid = threadIdx.x;
    int m0  = blockIdx.x * 128;
    int w = tid >> 5, lane = tid & 31, gq = lane >> 2, tig = lane & 3;
    if (tid < 128) {
        int m = m0 + tid; if (m >= E) m = E - 1;
        cS[tid] = g_colS[m]; rS[tid] = g_rowS[m]; sS[tid] = g_segS[m];
    }
    __syncthreads();

    float acc[8][4];
#pragma unroll
    for (int i = 0; i < 8; i++)
#pragma unroll
        for (int j = 0; j < 4; j++) acc[i][j] = 0.f;

    int rA   = tid >> 1;
    int half = tid & 1;
    int cA = cS[rA], rB = rS[rA], sgA = sS[rA];

    for (int kc = 0; kc < 8; kc++) {
        // ---- stage A: gather + normalize + relu + bf16 split (128 x 32) ----
        {
            int kb = kc * 32 + half * 16;
            const float* pB  = &g_P[(size_t)cA * 256 + kb];
            const float* qB  = &g_Q[(size_t)rB * 256 + kb];
            const float* muB = &g_mean1[sgA * 256 + kb];
            const float* rsB = &g_rstd1[sgA * 256 + kb];
#pragma unroll
            for (int q = 0; q < 4; q++) {
                float4 p  = *(const float4*)(pB + q * 4);
                float4 qv = *(const float4*)(qB + q * 4);
                float4 mu = *(const float4*)(muB + q * 4);
                float4 rs = *(const float4*)(rsB + q * 4);
                float v0 = fmaxf((p.x + qv.x - mu.x) * rs.x, 0.f);
                float v1 = fmaxf((p.y + qv.y - mu.y) * rs.y, 0.f);
                float v2 = fmaxf((p.z + qv.z - mu.z) * rs.z, 0.f);
                float v3 = fmaxf((p.w + qv.w - mu.w) * rs.w, 0.f);
                float h0, l0, h1, l1, h2, l2, h3, l3;
                bsplit(v0, h0, l0); bsplit(v1, h1, l1);
                bsplit(v2, h2, l2); bsplit(v3, h3, l3);
                int o = rA * 20 + half * 8 + q * 2;
                Ah[o]     = pkbf(h0, h1);
                Ah[o + 1] = pkbf(h2, h3);
                Al[o]     = pkbf(l0, l1);
                Al[o + 1] = pkbf(l2, l3);
            }
        }
        // ---- stage B: copy pre-split W2 chunk --------------------------------
#pragma unroll
        for (int i = tid; i < 1024; i += 256) {
            int n = i >> 4, k2 = i & 15;
            Bh[n * 20 + k2] = g_W2ph[kc * 1024 + i];
            Bl[n * 20 + k2] = g_W2pl[kc * 1024 + i];
        }
        __syncthreads();
        // ---- MMA ----------------------------------------------------------------
        int r0 = w * 16;
#pragma unroll
        for (int ks = 0; ks < 2; ks++) {
            int kb = ks * 8;
            uint32_t ah0 = Ah[(r0 + gq) * 20 + kb + tig];
            uint32_t ah1 = Ah[(r0 + gq + 8) * 20 + kb + tig];
            uint32_t ah2 = Ah[(r0 + gq) * 20 + kb + tig + 4];
            uint32_t ah3 = Ah[(r0 + gq + 8) * 20 + kb + tig + 4];
            uint32_t al0 = Al[(r0 + gq) * 20 + kb + tig];
            uint32_t al1 = Al[(r0 + gq + 8) * 20 + kb + tig];
            uint32_t al2 = Al[(r0 + gq) * 20 + kb + tig + 4];
            uint32_t al3 = Al[(r0 + gq + 8) * 20 + kb + tig + 4];
#pragma unroll
            for (int nt = 0; nt < 8; nt++) {
                int nrow = nt * 8 + gq;
                uint32_t bh0 = Bh[nrow * 20 + kb + tig];
                uint32_t bh1 = Bh[nrow * 20 + kb + tig + 4];
                uint32_t bl0 = Bl[nrow * 20 + kb + tig];
                uint32_t bl1 = Bl[nrow * 20 + kb + tig + 4];
                mma16816(acc[nt], ah0, ah1, ah2, ah3, bh0, bh1);
                mma16816(acc[nt], ah0, ah1, ah2, ah3, bl0, bl1);
                mma16816(acc[nt], al0, al1, al2, al3, bh0, bh1);
            }
        }
        __syncthreads();
    }
    // ---- epilogue --------------------------------------------------------------
    int row0 = m0 + w * 16 + gq;
    int row1 = row0 + 8;
#pragma unroll
    for (int nt = 0; nt < 8; nt++) {
        int cidx = nt * 8 + tig * 2;
        if (row0 < E)
            *(float2*)&g_h2[(size_t)row0 * 64 + cidx] = make_float2(acc[nt][0], acc[nt][1]);
        if (row1 < E)
            *(float2*)&g_h2[(size_t)row1 * 64 + cidx] = make_float2(acc[nt][2], acc[nt][3]);
    }
}

// ---------------- K: stats of h2 ----------------------------------------------
__global__ void k_stats2() {
    int g  = blockIdx.x;
    int c0 = blockIdx.y * 32;
    int lane = threadIdx.x & 31, w = threadIdx.x >> 5;
    int start = g_off[g], end = g_off[g + 1];
    int ch = c0 + lane;
    float s1 = 0.f, s2 = 0.f;
    int m = start + w;
    for (; m + 8 < end; m += 16) {
        float va = g_h2[(size_t)m * 64 + ch];
        float vb = g_h2[(size_t)(m + 8) * 64 + ch];
        s1 += va + vb; s2 += va * va + vb * vb;
    }
    if (m < end) {
        float v = g_h2[(size_t)m * 64 + ch];
        s1 += v; s2 += v * v;
    }
    __shared__ float a1[8][32], a2[8][32];
    a1[w][lane] = s1; a2[w][lane] = s2;
    __syncthreads();
    if (w == 0) {
#pragma unroll
        for (int t = 1; t < 8; t++) { s1 += a1[t][lane]; s2 += a2[t][lane]; }
        int cnti = end - start; if (cnti < 1) cnti = 1;
        float cnt  = (float)cnti;
        float mean = s1 / cnt;
        float var  = fmaxf(s2 / cnt - mean * mean, 0.f);
        g_mean2[g * 64 + ch] = mean;
        g_rstd2[g * 64 + ch] = rsqrtf(var + EPS);
    }
}

// ---------------- K: out[perm[m]] = relu(norm2(h2)) . W3 + b3 ----------------
__global__ void k_final(const float* __restrict__ W3,
                        const float* __restrict__ b3,
                        float* __restrict__ out, int E) {
    __shared__ __align__(16) float sm[128 * 65];
    __shared__ float w3s[64];
    __shared__ int   sS[128];
    int tid = threadIdx.x;   // 128
    int m0  = blockIdx.x * 128;
    if (tid < 64) w3s[tid] = W3[tid];
    {
        int m = m0 + tid; if (m >= E) m = E - 1;
        sS[tid] = g_segS[m];
    }
    __syncthreads();
#pragma unroll
    for (int t = tid; t < 128 * 16; t += 128) {
        int rr = t >> 4, q = t & 15;
        int m = m0 + rr; if (m >= E) m = E - 1;
        float4 v  = *(const float4*)&g_h2[(size_t)m * 64 + q * 4];
        int s = sS[rr];
        float4 mu = *(const float4*)&g_mean2[s * 64 + q * 4];
        float4 rs = *(const float4*)&g_rstd2[s * 64 + q * 4];
        float* d = &sm[rr * 65 + q * 4];
        d[0] = fmaxf((v.x - mu.x) * rs.x, 0.f);
        d[1] = fmaxf((v.y - mu.y) * rs.y, 0.f);
        d[2] = fmaxf((v.z - mu.z) * rs.z, 0.f);
        d[3] = fmaxf((v.w - mu.w) * rs.w, 0.f);
    }
    __syncthreads();
    int m = m0 + tid;
    if (m < E) {
        float acc = 0.f;
#pragma unroll
        for (int k = 0; k < 64; k++) acc += sm[tid * 65 + k] * w3s[k];
        out[g_perm[m]] = acc + b3[0];
    }
}

// ---------------- launch -------------------------------------------------------
extern "C" void kernel_launch(void* const* d_in, const int* in_sizes, int n_in,
                              void* d_out, int out_size) {
    const float* emb = (const float*)d_in[0];
    const void*  ei  = d_in[1];
    const void*  bt  = d_in[2];
    const float* W1  = (const float*)d_in[3];
    // d_in[4] = b1 : cancels exactly through affine-free InstanceNorm
    const float* W2  = (const float*)d_in[5];
    // d_in[6] = b2 : cancels exactly through affine-free InstanceNorm
    const float* W3  = (const float*)d_in[7];
    const float* b3  = (const float*)d_in[8];
    float* out = (float*)d_out;

    int Nn = in_sizes[0] / 64;
    int E  = in_sizes[1] / 2;

    k_edges<<<(E + 255) / 256, 256>>>(ei, E, Nn);                // 1
    k_wcvt<<<96, 256>>>(W1, W2);                                 // 2
    k_scan_node<<<1, 1024>>>(bt, E, Nn);                         // 3 (self-clearing)
    dim3 gPQ((Nn + 127) / 128, 4, 2);
    k_pqm<<<gPQ, 256>>>(emb, Nn);                                // 4 (profiled)
    k_scatter<<<(E + 255) / 256, 256>>>(bt, E);                  // 5
    k_stats1<<<dim3(128, 8), 256>>>();                           // 6
    k_gemm2<<<(E + 127) / 128, 256>>>(E);                        // 7
    k_stats2<<<dim3(128, 2), 256>>>();                           // 8
    k_final<<<(E + 127) / 128, 128>>>(W3, b3, out, E);           // 9
}

// round 8
// speedup vs baseline: 1.2426x; 1.0339x over previous
#include <cuda_runtime.h>
#include <cuda_bf16.h>
#include <cstdint>

#define EPS 1e-5f
#define NGRAPH 128
#define EMAX 800000
#define NMAX 50000

// ---------------- scratch (__device__ globals; no allocation allowed) -------
__device__ int g_is64_bt;
__device__ int g_nodeCnt[NMAX];
__device__ int g_nodeOff[NMAX];
__device__ int g_cursorN[NMAX];
__device__ int g_off[NGRAPH + 1];
__device__ int g_col[EMAX];
__device__ int g_row[EMAX];
__device__ int g_perm[EMAX];
__device__ int g_segS[EMAX];
__device__ int g_colS[EMAX];
__device__ int g_rowS[EMAX];
__device__ __align__(16) float g_P[NMAX * 256];   // emb @ W1[:64 ,:]
__device__ __align__(16) float g_Q[NMAX * 256];   // emb @ W1[64:,:]
__device__ __align__(16) uint32_t g_Pb[NMAX * 128];  // bf16x2 copy of P
__device__ __align__(16) uint32_t g_Qb[NMAX * 128];  // bf16x2 copy of Q
__device__ __align__(16) float g_h2[(size_t)EMAX * 64];
__device__ __align__(16) float g_mean1[NGRAPH * 256];
__device__ __align__(16) float g_rstd1[NGRAPH * 256];
__device__ __align__(16) float g_mean2[NGRAPH * 64];
__device__ __align__(16) float g_rstd2[NGRAPH * 64];
// W2 pre-split bf16 hi/lo packed b32: [kc 8][n 64][k2 16]
__device__ __align__(16) uint32_t g_W2ph[8192];
__device__ __align__(16) uint32_t g_W2pl[8192];
// W1 pre-split bf16 hi/lo packed b32: [z 2][nb 4][kc 2][n 64][k2 16]
__device__ __align__(16) uint32_t g_W1ph[16384];
__device__ __align__(16) uint32_t g_W1pl[16384];

// ---------------- helpers ----------------------------------------------------
__device__ __forceinline__ uint32_t pkbf(float a, float b) {
    __nv_bfloat162 h = __floats2bfloat162_rn(a, b);
    return *(uint32_t*)&h;
}
__device__ __forceinline__ float2 upbf(uint32_t u) {
    __nv_bfloat162 h = *(__nv_bfloat162*)&u;
    return make_float2(__bfloat162float(h.x), __bfloat162float(h.y));
}
__device__ __forceinline__ void bsplit(float v, float& hi, float& lo) {
    __nv_bfloat16 h = __float2bfloat16(v);
    hi = __bfloat162float(h);
    lo = v - hi;
}
__device__ __forceinline__ void mma16816(float* c, uint32_t a0, uint32_t a1,
                                         uint32_t a2, uint32_t a3,
                                         uint32_t b0, uint32_t b1) {
    asm volatile(
        "mma.sync.aligned.m16n8k16.row.col.f32.bf16.bf16.f32 "
        "{%0,%1,%2,%3}, {%4,%5,%6,%7}, {%8,%9}, {%0,%1,%2,%3};"
        : "+f"(c[0]), "+f"(c[1]), "+f"(c[2]), "+f"(c[3])
        : "r"(a0), "r"(a1), "r"(a2), "r"(a3), "r"(b0), "r"(b1));
}

// ---------------- K1: prep = W1/W2 split (blocks 0..95) + edge decode --------
__global__ void k_prep(const void* __restrict__ ei_raw,
                       const float* __restrict__ W1,
                       const float* __restrict__ W2, int E, int Nn) {
    int bid = blockIdx.x;
    int t = threadIdx.x;               // 256
    if (bid < 96) {
        int i = bid * 256 + t;          // 24576 total
        if (i < 16384) {
            int z  = i >> 13;
            int nb = (i >> 11) & 3;
            int kc = (i >> 10) & 1;
            int n  = (i >> 4) & 63;
            int k2 = i & 15;
            int kk  = z * 64 + kc * 32 + k2 * 2;
            int col = nb * 64 + n;
            float wa = W1[kk * 256 + col];
            float wb = W1[(kk + 1) * 256 + col];
            float ha, la, hb, lb;
            bsplit(wa, ha, la); bsplit(wb, hb, lb);
            g_W1ph[i] = pkbf(ha, hb);
            g_W1pl[i] = pkbf(la, lb);
        } else {
            int j = i - 16384;
            int kc = j >> 10, n = (j >> 4) & 63, k2 = j & 15;
            int kk = kc * 32 + k2 * 2;
            float wa = W2[kk * 64 + n];
            float wb = W2[(kk + 1) * 64 + n];
            float ha, la, hb, lb;
            bsplit(wa, ha, la); bsplit(wb, hb, lb);
            g_W2ph[j] = pkbf(ha, hb);
            g_W2pl[j] = pkbf(la, lb);
        }
        return;
    }
    // edge decode + node histogram
    __shared__ int s_nz;
    if (t == 0) s_nz = 0;
    __syncthreads();
    const int* ei32 = (const int*)ei_raw;
    if (ei32[2 * t + 1]) atomicOr(&s_nz, 1);
    __syncthreads();
    bool e64 = (s_nz == 0);
    int e = (bid - 96) * 256 + t;
    if (e >= E) return;
    int ci, ri;
    if (e64) {
        ci = (int)((const long long*)ei_raw)[e];
        ri = (int)((const long long*)ei_raw)[(size_t)E + e];
    } else {
        ci = ei32[e];
        ri = ei32[E + e];
    }
    ci = min(max(ci, 0), Nn - 1);
    ri = min(max(ri, 0), Nn - 1);
    g_col[e] = ci; g_row[e] = ri;
    atomicAdd(&g_nodeCnt[ci], 1);
}

// ---------------- K2: tile-scan (self-clearing) + graph offsets + bt detect ---
__global__ void k_scan_node(const void* __restrict__ bt_raw, int E, int Nn) {
    __shared__ int warpSum[32];
    __shared__ int s_bt, s_carry;
    int t = threadIdx.x;               // 1024
    int lane = t & 31, w = t >> 5;
    if (t == 0) { s_bt = 0; s_carry = 0; }
    __syncthreads();
    {
        const int* bt32 = (const int*)bt_raw;
        int lim = Nn / 2 < 16384 ? Nn / 2 : 16384;
        int nz = 0;
        for (int i = t; i < lim; i += 1024) nz |= bt32[2 * i + 1];
        for (int d = 16; d; d >>= 1) nz |= __shfl_xor_sync(~0u, nz, d);
        if (lane == 0 && nz) atomicOr(&s_bt, 1);
    }
    __syncthreads();
    bool b64 = (s_bt == 0);
    if (t == 0) g_is64_bt = b64 ? 1 : 0;

    int ntile = (Nn + 4095) >> 12;
    for (int tile = 0; tile < ntile; tile++) {
        int idx0 = (tile << 12) + t * 4;
        int c0 = 0, c1 = 0, c2 = 0, c3 = 0;
        if (idx0 + 3 < Nn) {
            int4 c = *(const int4*)&g_nodeCnt[idx0];
            c0 = c.x; c1 = c.y; c2 = c.z; c3 = c.w;
            int4 z = make_int4(0, 0, 0, 0);
            *(int4*)&g_nodeCnt[idx0] = z;            // self-clear for next replay
        } else {
            if (idx0 + 0 < Nn) { c0 = g_nodeCnt[idx0 + 0]; g_nodeCnt[idx0 + 0] = 0; }
            if (idx0 + 1 < Nn) { c1 = g_nodeCnt[idx0 + 1]; g_nodeCnt[idx0 + 1] = 0; }
            if (idx0 + 2 < Nn) { c2 = g_nodeCnt[idx0 + 2]; g_nodeCnt[idx0 + 2] = 0; }
            if (idx0 + 3 < Nn) { c3 = g_nodeCnt[idx0 + 3]; g_nodeCnt[idx0 + 3] = 0; }
        }
        int s = c0 + c1 + c2 + c3;
        int v = s;
        for (int d = 1; d < 32; d <<= 1) {
            int u = __shfl_up_sync(~0u, v, d);
            if (lane >= d) v += u;
        }
        if (lane == 31) warpSum[w] = v;
        __syncthreads();
        if (w == 0) {
            int x = warpSum[lane];
            for (int d = 1; d < 32; d <<= 1) {
                int u = __shfl_up_sync(~0u, x, d);
                if (lane >= d) x += u;
            }
            warpSum[lane] = x;
        }
        __syncthreads();
        int warpExcl = w ? warpSum[w - 1] : 0;
        int run = s_carry + warpExcl + (v - s);
        if (idx0 + 0 < Nn) { g_nodeOff[idx0 + 0] = run; g_cursorN[idx0 + 0] = run; run += c0; }
        if (idx0 + 1 < Nn) { g_nodeOff[idx0 + 1] = run; g_cursorN[idx0 + 1] = run; run += c1; }
        if (idx0 + 2 < Nn) { g_nodeOff[idx0 + 2] = run; g_cursorN[idx0 + 2] = run; run += c2; }
        if (idx0 + 3 < Nn) { g_nodeOff[idx0 + 3] = run; g_cursorN[idx0 + 3] = run; run += c3; }
        __syncthreads();
        if (t == 0) s_carry += warpSum[31];
        __syncthreads();
    }
    if (t < NGRAPH) {
        int lo = 0, hi = Nn;
        while (lo < hi) {
            int mid = (lo + hi) >> 1;
            long long bv = b64 ? ((const long long*)bt_raw)[mid]
                               : (long long)((const int*)bt_raw)[mid];
            if (bv < (long long)t) lo = mid + 1; else hi = mid;
        }
        g_off[t] = (lo < Nn) ? g_nodeOff[lo] : E;
    }
    if (t == 0) g_off[NGRAPH] = E;
}

// ---------------- K3: scatter (blocks 0..nS-1) + P/Q MMA (rest) --------------
__global__ void __launch_bounds__(256) k_sp(const void* __restrict__ bt_raw,
                                            const float* __restrict__ emb,
                                            int E, int Nn, int nS) {
    __shared__ uint32_t Ah[128 * 20];
    __shared__ uint32_t Al[128 * 20];
    __shared__ uint32_t Bh[64 * 20];
    __shared__ uint32_t Bl[64 * 20];
    int tid = threadIdx.x;
    if ((int)blockIdx.x < nS) {
        int e = blockIdx.x * 256 + tid;
        if (e >= E) return;
        int ci = g_col[e];
        int pos = atomicAdd(&g_cursorN[ci], 1);
        bool b64 = (g_is64_bt != 0);
        int sg = b64 ? (int)((const long long*)bt_raw)[ci]
                     : ((const int*)bt_raw)[ci];
        sg = min(max(sg, 0), NGRAPH - 1);
        g_perm[pos] = e;
        g_colS[pos] = ci;
        g_rowS[pos] = g_row[e];
        g_segS[pos] = sg;
        return;
    }
    // ---- P/Q MMA branch -------------------------------------------------------
    int idx = blockIdx.x - nS;
    int m0  = (idx >> 3) * 128;
    int nb  = (idx >> 1) & 3;
    int z   = idx & 1;
    int w = tid >> 5, lane = tid & 31, gq = lane >> 2, tig = lane & 3;

    float acc[8][4];
#pragma unroll
    for (int i = 0; i < 8; i++)
#pragma unroll
        for (int j = 0; j < 4; j++) acc[i][j] = 0.f;

    int rA   = tid >> 1;
    int half = tid & 1;
    int node = min(m0 + rA, Nn - 1);
    const uint32_t* w1h = &g_W1ph[(size_t)((z * 4 + nb) * 2) * 1024];
    const uint32_t* w1l = &g_W1pl[(size_t)((z * 4 + nb) * 2) * 1024];

    for (int kc = 0; kc < 2; kc++) {
        {
            const float* er = &emb[(size_t)node * 64 + kc * 32 + half * 16];
#pragma unroll
            for (int q = 0; q < 4; q++) {
                float4 v = *(const float4*)(er + q * 4);
                float h0, l0, h1, l1, h2, l2, h3, l3;
                bsplit(v.x, h0, l0); bsplit(v.y, h1, l1);
                bsplit(v.z, h2, l2); bsplit(v.w, h3, l3);
                int o = rA * 20 + half * 8 + q * 2;
                Ah[o]     = pkbf(h0, h1);
                Ah[o + 1] = pkbf(h2, h3);
                Al[o]     = pkbf(l0, l1);
                Al[o + 1] = pkbf(l2, l3);
            }
        }
#pragma unroll
        for (int i = tid; i < 1024; i += 256) {
            int n = i >> 4, k2 = i & 15;
            Bh[n * 20 + k2] = w1h[kc * 1024 + i];
            Bl[n * 20 + k2] = w1l[kc * 1024 + i];
        }
        __syncthreads();
        int r0 = w * 16;
#pragma unroll
        for (int ks = 0; ks < 2; ks++) {
            int kb = ks * 8;
            uint32_t ah0 = Ah[(r0 + gq) * 20 + kb + tig];
            uint32_t ah1 = Ah[(r0 + gq + 8) * 20 + kb + tig];
            uint32_t ah2 = Ah[(r0 + gq) * 20 + kb + tig + 4];
            uint32_t ah3 = Ah[(r0 + gq + 8) * 20 + kb + tig + 4];
            uint32_t al0 = Al[(r0 + gq) * 20 + kb + tig];
            uint32_t al1 = Al[(r0 + gq + 8) * 20 + kb + tig];
            uint32_t al2 = Al[(r0 + gq) * 20 + kb + tig + 4];
            uint32_t al3 = Al[(r0 + gq + 8) * 20 + kb + tig + 4];
#pragma unroll
            for (int nt = 0; nt < 8; nt++) {
                int nrow = nt * 8 + gq;
                uint32_t bh0 = Bh[nrow * 20 + kb + tig];
                uint32_t bh1 = Bh[nrow * 20 + kb + tig + 4];
                uint32_t bl0 = Bl[nrow * 20 + kb + tig];
                uint32_t bl1 = Bl[nrow * 20 + kb + tig + 4];
                mma16816(acc[nt], ah0, ah1, ah2, ah3, bh0, bh1);
                mma16816(acc[nt], ah0, ah1, ah2, ah3, bl0, bl1);
                mma16816(acc[nt], al0, al1, al2, al3, bh0, bh1);
            }
        }
        __syncthreads();
    }
    float*    dst  = z ? g_Q : g_P;
    uint32_t* dstb = z ? g_Qb : g_Pb;
    int row0 = m0 + w * 16 + gq;
    int row1 = row0 + 8;
#pragma unroll
    for (int nt = 0; nt < 8; nt++) {
        int cidx = nb * 64 + nt * 8 + tig * 2;
        if (row0 < Nn) {
            *(float2*)&dst[(size_t)row0 * 256 + cidx] = make_float2(acc[nt][0], acc[nt][1]);
            dstb[(size_t)row0 * 128 + (cidx >> 1)] = pkbf(acc[nt][0], acc[nt][1]);
        }
        if (row1 < Nn) {
            *(float2*)&dst[(size_t)row1 * 256 + cidx] = make_float2(acc[nt][2], acc[nt][3]);
            dstb[(size_t)row1 * 128 + (cidx >> 1)] = pkbf(acc[nt][2], acc[nt][3]);
        }
    }
}

// ---------------- K4: stats of h1 from bf16 P/Q (profiled slot) ---------------
// grid (128 graphs, 4); block 256 = 8 warps; warp covers 64 channels (32 u32).
__global__ void k_stats1() {
    int g   = blockIdx.x;
    int c0u = blockIdx.y * 32;          // u32 column base (channels 2*c0u..)
    int lane = threadIdx.x & 31, w = threadIdx.x >> 5;
    int start = g_off[g], end = g_off[g + 1];
    float s1a = 0.f, s1b = 0.f, s2a = 0.f, s2b = 0.f;
    int m = start + w;
    for (; m + 8 < end; m += 16) {
        uint32_t pu0 = g_Pb[(size_t)g_colS[m] * 128 + c0u + lane];
        uint32_t qu0 = g_Qb[(size_t)g_rowS[m] * 128 + c0u + lane];
        uint32_t pu1 = g_Pb[(size_t)g_colS[m + 8] * 128 + c0u + lane];
        uint32_t qu1 = g_Qb[(size_t)g_rowS[m + 8] * 128 + c0u + lane];
        float2 p0 = upbf(pu0), q0 = upbf(qu0);
        float2 p1 = upbf(pu1), q1 = upbf(qu1);
        float va0 = p0.x + q0.x, vb0 = p0.y + q0.y;
        float va1 = p1.x + q1.x, vb1 = p1.y + q1.y;
        s1a += va0 + va1; s2a += va0 * va0 + va1 * va1;
        s1b += vb0 + vb1; s2b += vb0 * vb0 + vb1 * vb1;
    }
    if (m < end) {
        uint32_t pu = g_Pb[(size_t)g_colS[m] * 128 + c0u + lane];
        uint32_t qu = g_Qb[(size_t)g_rowS[m] * 128 + c0u + lane];
        float2 p = upbf(pu), q = upbf(qu);
        float va = p.x + q.x, vb = p.y + q.y;
        s1a += va; s2a += va * va;
        s1b += vb; s2b += vb * vb;
    }
    __shared__ float r1a[8][32], r1b[8][32], r2a[8][32], r2b[8][32];
    r1a[w][lane] = s1a; r1b[w][lane] = s1b;
    r2a[w][lane] = s2a; r2b[w][lane] = s2b;
    __syncthreads();
    if (w == 0) {
#pragma unroll
        for (int t = 1; t < 8; t++) {
            s1a += r1a[t][lane]; s1b += r1b[t][lane];
            s2a += r2a[t][lane]; s2b += r2b[t][lane];
        }
        int cnti = end - start; if (cnti < 1) cnti = 1;
        float inv = 1.f / (float)cnti;
        float ma = s1a * inv, mb = s1b * inv;
        float va = fmaxf(s2a * inv - ma * ma, 0.f);
        float vb = fmaxf(s2b * inv - mb * mb, 0.f);
        int ch = (c0u + lane) * 2;
        g_mean1[g * 256 + ch]     = ma;
        g_mean1[g * 256 + ch + 1] = mb;
        g_rstd1[g * 256 + ch]     = rsqrtf(va + EPS);
        g_rstd1[g * 256 + ch + 1] = rsqrtf(vb + EPS);
    }
}

// ---------------- K5: h2 via direct-load bf16 3-term MMA ----------------------
__global__ void __launch_bounds__(256) k_gemm2(int E) {
    __shared__ uint32_t Ah[128 * 20];
    __shared__ uint32_t Al[128 * 20];
    __shared__ uint32_t Bh[64 * 20];
    __shared__ uint32_t Bl[64 * 20];
    __shared__ int cS[128], rS[128], sS[128];
    int tid = threadIdx.x;
    int m0  = blockIdx.x * 128;
    int w = tid >> 5, lane = tid & 31, gq = lane >> 2, tig = lane & 3;
    if (tid < 128) {
        int m = m0 + tid; if (m >= E) m = E - 1;
        cS[tid] = g_colS[m]; rS[tid] = g_rowS[m]; sS[tid] = g_segS[m];
    }
    __syncthreads();

    float acc[8][4];
#pragma unroll
    for (int i = 0; i < 8; i++)
#pragma unroll
        for (int j = 0; j < 4; j++) acc[i][j] = 0.f;

    int rA   = tid >> 1;
    int half = tid & 1;
    int cA = cS[rA], rB = rS[rA], sgA = sS[rA];

    for (int kc = 0; kc < 8; kc++) {
        {
            int kb = kc * 32 + half * 16;
            const float* pB  = &g_P[(size_t)cA * 256 + kb];
            const float* qB  = &g_Q[(size_t)rB * 256 + kb];
            const float* muB = &g_mean1[sgA * 256 + kb];
            const float* rsB = &g_rstd1[sgA * 256 + kb];
#pragma unroll
            for (int q = 0; q < 4; q++) {
                float4 p  = *(const float4*)(pB + q * 4);
                float4 qv = *(const float4*)(qB + q * 4);
                float4 mu = *(const float4*)(muB + q * 4);
                float4 rs = *(const float4*)(rsB + q * 4);
                float v0 = fmaxf((p.x + qv.x - mu.x) * rs.x, 0.f);
                float v1 = fmaxf((p.y + qv.y - mu.y) * rs.y, 0.f);
                float v2 = fmaxf((p.z + qv.z - mu.z) * rs.z, 0.f);
                float v3 = fmaxf((p.w + qv.w - mu.w) * rs.w, 0.f);
                float h0, l0, h1, l1, h2, l2, h3, l3;
                bsplit(v0, h0, l0); bsplit(v1, h1, l1);
                bsplit(v2, h2, l2); bsplit(v3, h3, l3);
                int o = rA * 20 + half * 8 + q * 2;
                Ah[o]     = pkbf(h0, h1);
                Ah[o + 1] = pkbf(h2, h3);
                Al[o]     = pkbf(l0, l1);
                Al[o + 1] = pkbf(l2, l3);
            }
        }
#pragma unroll
        for (int i = tid; i < 1024; i += 256) {
            int n = i >> 4, k2 = i & 15;
            Bh[n * 20 + k2] = g_W2ph[kc * 1024 + i];
            Bl[n * 20 + k2] = g_W2pl[kc * 1024 + i];
        }
        __syncthreads();
        int r0 = w * 16;
#pragma unroll
        for (int ks = 0; ks < 2; ks++) {
            int kb = ks * 8;
            uint32_t ah0 = Ah[(r0 + gq) * 20 + kb + tig];
            uint32_t ah1 = Ah[(r0 + gq + 8) * 20 + kb + tig];
            uint32_t ah2 = Ah[(r0 + gq) * 20 + kb + tig + 4];
            uint32_t ah3 = Ah[(r0 + gq + 8) * 20 + kb + tig + 4];
            uint32_t al0 = Al[(r0 + gq) * 20 + kb + tig];
            uint32_t al1 = Al[(r0 + gq + 8) * 20 + kb + tig];
            uint32_t al2 = Al[(r0 + gq) * 20 + kb + tig + 4];
            uint32_t al3 = Al[(r0 + gq + 8) * 20 + kb + tig + 4];
#pragma unroll
            for (int nt = 0; nt < 8; nt++) {
                int nrow = nt * 8 + gq;
                uint32_t bh0 = Bh[nrow * 20 + kb + tig];
                uint32_t bh1 = Bh[nrow * 20 + kb + tig + 4];
                uint32_t bl0 = Bl[nrow * 20 + kb + tig];
                uint32_t bl1 = Bl[nrow * 20 + kb + tig + 4];
                mma16816(acc[nt], ah0, ah1, ah2, ah3, bh0, bh1);
                mma16816(acc[nt], ah0, ah1, ah2, ah3, bl0, bl1);
                mma16816(acc[nt], al0, al1, al2, al3, bh0, bh1);
            }
        }
        __syncthreads();
    }
    // ---- epilogue: streaming stores (keep P/Q resident in L2) -----------------
    int row0 = m0 + w * 16 + gq;
    int row1 = row0 + 8;
#pragma unroll
    for (int nt = 0; nt < 8; nt++) {
        int cidx = nt * 8 + tig * 2;
        if (row0 < E)
            __stcs((float2*)&g_h2[(size_t)row0 * 64 + cidx],
                   make_float2(acc[nt][0], acc[nt][1]));
        if (row1 < E)
            __stcs((float2*)&g_h2[(size_t)row1 * 64 + cidx],
                   make_float2(acc[nt][2], acc[nt][3]));
    }
}

// ---------------- K6: stats of h2 ----------------------------------------------
__global__ void k_stats2() {
    int g  = blockIdx.x;
    int c0 = blockIdx.y * 32;
    int lane = threadIdx.x & 31, w = threadIdx.x >> 5;
    int start = g_off[g], end = g_off[g + 1];
    int ch = c0 + lane;
    float s1 = 0.f, s2 = 0.f;
    int m = start + w;
    for (; m + 8 < end; m += 16) {
        float va = g_h2[(size_t)m * 64 + ch];
        float vb = g_h2[(size_t)(m + 8) * 64 + ch];
        s1 += va + vb; s2 += va * va + vb * vb;
    }
    if (m < end) {
        float v = g_h2[(size_t)m * 64 + ch];
        s1 += v; s2 += v * v;
    }
    __shared__ float a1[8][32], a2[8][32];
    a1[w][lane] = s1; a2[w][lane] = s2;
    __syncthreads();
    if (w == 0) {
#pragma unroll
        for (int t = 1; t < 8; t++) { s1 += a1[t][lane]; s2 += a2[t][lane]; }
        int cnti = end - start; if (cnti < 1) cnti = 1;
        float cnt  = (float)cnti;
        float mean = s1 / cnt;
        float var  = fmaxf(s2 / cnt - mean * mean, 0.f);
        g_mean2[g * 64 + ch] = mean;
        g_rstd2[g * 64 + ch] = rsqrtf(var + EPS);
    }
}

// ---------------- K7: out[perm[m]] = relu(norm2(h2)) . W3 + b3 -----------------
__global__ void k_final(const float* __restrict__ W3,
                        const float* __restrict__ b3,
                        float* __restrict__ out, int E) {
    __shared__ __align__(16) float sm[128 * 65];
    __shared__ float w3s[64];
    __shared__ int   sS[128];
    int tid = threadIdx.x;   // 128
    int m0  = blockIdx.x * 128;
    if (tid < 64) w3s[tid] = W3[tid];
    {
        int m = m0 + tid; if (m >= E) m = E - 1;
        sS[tid] = g_segS[m];
    }
    __syncthreads();
#pragma unroll
    for (int t = tid; t < 128 * 16; t += 128) {
        int rr = t >> 4, q = t & 15;
        int m = m0 + rr; if (m >= E) m = E - 1;
        float4 v  = __ldcs((const float4*)&g_h2[(size_t)m * 64 + q * 4]);
        int s = sS[rr];
        float4 mu = *(const float4*)&g_mean2[s * 64 + q * 4];
        float4 rs = *(const float4*)&g_rstd2[s * 64 + q * 4];
        float* d = &sm[rr * 65 + q * 4];
        d[0] = fmaxf((v.x - mu.x) * rs.x, 0.f);
        d[1] = fmaxf((v.y - mu.y) * rs.y, 0.f);
        d[2] = fmaxf((v.z - mu.z) * rs.z, 0.f);
        d[3] = fmaxf((v.w - mu.w) * rs.w, 0.f);
    }
    __syncthreads();
    int m = m0 + tid;
    if (m < E) {
        float acc = 0.f;
#pragma unroll
        for (int k = 0; k < 64; k++) acc += sm[tid * 65 + k] * w3s[k];
        out[g_perm[m]] = acc + b3[0];
    }
}

// ---------------- launch ---------------------------------------------------------
extern "C" void kernel_launch(void* const* d_in, const int* in_sizes, int n_in,
                              void* d_out, int out_size) {
    const float* emb = (const float*)d_in[0];
    const void*  ei  = d_in[1];
    const void*  bt  = d_in[2];
    const float* W1  = (const float*)d_in[3];
    // d_in[4] = b1 : cancels exactly through affine-free InstanceNorm
    const float* W2  = (const float*)d_in[5];
    // d_in[6] = b2 : cancels exactly through affine-free InstanceNorm
    const float* W3  = (const float*)d_in[7];
    const float* b3  = (const float*)d_in[8];
    float* out = (float*)d_out;

    int Nn = in_sizes[0] / 64;
    int E  = in_sizes[1] / 2;

    int nEdgeBlk = (E + 255) / 256;
    int nPqBlk   = ((Nn + 127) / 128) * 8;

    k_prep<<<96 + nEdgeBlk, 256>>>(ei, W1, W2, E, Nn);           // 1
    k_scan_node<<<1, 1024>>>(bt, E, Nn);                         // 2
    k_sp<<<nEdgeBlk + nPqBlk, 256>>>(bt, emb, E, Nn, nEdgeBlk);  // 3
    k_stats1<<<dim3(128, 4), 256>>>();                           // 4 (profiled)
    k_gemm2<<<(E + 127) / 128, 256>>>(E);                        // 5
    k_stats2<<<dim3(128, 2), 256>>>();                           // 6
    k_final<<<(E + 127) / 128, 128>>>(W3, b3, out, E);           // 7
}

// round 9
// speedup vs baseline: 1.4475x; 1.1649x over previous
#include <cuda_runtime.h>
#include <cuda_bf16.h>
#include <cstdint>

#define EPS 1e-5f
#define NGRAPH 128
#define EMAX 800000
#define NMAX 50000
#define SPLIT1 8
#define SPLIT2 8

// ---------------- scratch (__device__ globals; no allocation allowed) -------
__device__ int g_is64_bt;
__device__ int g_nodeCnt[NMAX];
__device__ int g_nodeOff[NMAX];
__device__ int g_cursorN[NMAX];
__device__ int g_off[NGRAPH + 1];
__device__ int g_col[EMAX];
__device__ int g_row[EMAX];
__device__ int g_perm[EMAX];
__device__ int g_segS[EMAX];
__device__ int g_colS[EMAX];
__device__ int g_rowS[EMAX];
__device__ __align__(16) float g_P[NMAX * 256];
__device__ __align__(16) float g_Q[NMAX * 256];
__device__ __align__(16) uint32_t g_Pb[NMAX * 128];  // bf16x2 copy of P
__device__ __align__(16) uint32_t g_Qb[NMAX * 128];  // bf16x2 copy of Q
__device__ __align__(16) float g_h2[(size_t)EMAX * 64];
__device__ __align__(16) float g_mean1[NGRAPH * 256];
__device__ __align__(16) float g_rstd1[NGRAPH * 256];
__device__ __align__(16) float g_mean2[NGRAPH * 64];
__device__ __align__(16) float g_rstd2[NGRAPH * 64];
// accumulators: s1[32768] s2[32768] t1[8192] t2[8192]
__device__ __align__(16) float g_acc[81920];
// W2 pre-split bf16 hi/lo packed b32: [kc 8][n 64][k2 16]
__device__ __align__(16) uint32_t g_W2ph[8192];
__device__ __align__(16) uint32_t g_W2pl[8192];
// W1 pre-split bf16 hi/lo packed b32: [z 2][nb 4][kc 2][n 64][k2 16]
__device__ __align__(16) uint32_t g_W1ph[16384];
__device__ __align__(16) uint32_t g_W1pl[16384];

// ---------------- helpers ----------------------------------------------------
__device__ __forceinline__ uint32_t pkbf(float a, float b) {
    __nv_bfloat162 h = __floats2bfloat162_rn(a, b);
    return *(uint32_t*)&h;
}
__device__ __forceinline__ float2 upbf(uint32_t u) {
    __nv_bfloat162 h = *(__nv_bfloat162*)&u;
    return make_float2(__bfloat162float(h.x), __bfloat162float(h.y));
}
__device__ __forceinline__ void bsplit(float v, float& hi, float& lo) {
    __nv_bfloat16 h = __float2bfloat16(v);
    hi = __bfloat162float(h);
    lo = v - hi;
}
__device__ __forceinline__ void mma16816(float* c, uint32_t a0, uint32_t a1,
                                         uint32_t a2, uint32_t a3,
                                         uint32_t b0, uint32_t b1) {
    asm volatile(
        "mma.sync.aligned.m16n8k16.row.col.f32.bf16.bf16.f32 "
        "{%0,%1,%2,%3}, {%4,%5,%6,%7}, {%8,%9}, {%0,%1,%2,%3};"
        : "+f"(c[0]), "+f"(c[1]), "+f"(c[2]), "+f"(c[3])
        : "r"(a0), "r"(a1), "r"(a2), "r"(a3), "r"(b0), "r"(b1));
}

// ---------------- K1: prep = W split | acc zero | edge decode ----------------
__global__ void k_prep(const void* __restrict__ ei_raw,
                       const float* __restrict__ W1,
                       const float* __restrict__ W2, int E, int Nn) {
    int bid = blockIdx.x;
    int t = threadIdx.x;               // 256
    if (bid < 96) {
        int i = bid * 256 + t;
        if (i < 16384) {
            int z  = i >> 13;
            int nb = (i >> 11) & 3;
            int kc = (i >> 10) & 1;
            int n  = (i >> 4) & 63;
            int k2 = i & 15;
            int kk  = z * 64 + kc * 32 + k2 * 2;
            int col = nb * 64 + n;
            float wa = W1[kk * 256 + col];
            float wb = W1[(kk + 1) * 256 + col];
            float ha, la, hb, lb;
            bsplit(wa, ha, la); bsplit(wb, hb, lb);
            g_W1ph[i] = pkbf(ha, hb);
            g_W1pl[i] = pkbf(la, lb);
        } else {
            int j = i - 16384;
            int kc = j >> 10, n = (j >> 4) & 63, k2 = j & 15;
            int kk = kc * 32 + k2 * 2;
            float wa = W2[kk * 64 + n];
            float wb = W2[(kk + 1) * 64 + n];
            float ha, la, hb, lb;
            bsplit(wa, ha, la); bsplit(wb, hb, lb);
            g_W2ph[j] = pkbf(ha, hb);
            g_W2pl[j] = pkbf(la, lb);
        }
        return;
    }
    if (bid < 176) {                    // zero 81920 floats = 20480 float4
        int i = (bid - 96) * 256 + t;
        *(float4*)&g_acc[i * 4] = make_float4(0.f, 0.f, 0.f, 0.f);
        return;
    }
    // edge decode + node histogram
    __shared__ int s_nz;
    if (t == 0) s_nz = 0;
    __syncthreads();
    const int* ei32 = (const int*)ei_raw;
    if (ei32[2 * t + 1]) atomicOr(&s_nz, 1);
    __syncthreads();
    bool e64 = (s_nz == 0);
    int e = (bid - 176) * 256 + t;
    if (e >= E) return;
    int ci, ri;
    if (e64) {
        ci = (int)((const long long*)ei_raw)[e];
        ri = (int)((const long long*)ei_raw)[(size_t)E + e];
    } else {
        ci = ei32[e];
        ri = ei32[E + e];
    }
    ci = min(max(ci, 0), Nn - 1);
    ri = min(max(ri, 0), Nn - 1);
    g_col[e] = ci; g_row[e] = ri;
    atomicAdd(&g_nodeCnt[ci], 1);
}

// ---------------- K2: tile-scan (self-clearing) + graph offsets + bt detect ---
__global__ void k_scan_node(const void* __restrict__ bt_raw, int E, int Nn) {
    __shared__ int warpSum[32];
    __shared__ int s_bt, s_carry;
    int t = threadIdx.x;               // 1024
    int lane = t & 31, w = t >> 5;
    if (t == 0) { s_bt = 0; s_carry = 0; }
    __syncthreads();
    {
        const int* bt32 = (const int*)bt_raw;
        int lim = Nn / 2 < 16384 ? Nn / 2 : 16384;
        int nz = 0;
        for (int i = t; i < lim; i += 1024) nz |= bt32[2 * i + 1];
        for (int d = 16; d; d >>= 1) nz |= __shfl_xor_sync(~0u, nz, d);
        if (lane == 0 && nz) atomicOr(&s_bt, 1);
    }
    __syncthreads();
    bool b64 = (s_bt == 0);
    if (t == 0) g_is64_bt = b64 ? 1 : 0;

    int ntile = (Nn + 4095) >> 12;
    for (int tile = 0; tile < ntile; tile++) {
        int idx0 = (tile << 12) + t * 4;
        int c0 = 0, c1 = 0, c2 = 0, c3 = 0;
        if (idx0 + 3 < Nn) {
            int4 c = *(const int4*)&g_nodeCnt[idx0];
            c0 = c.x; c1 = c.y; c2 = c.z; c3 = c.w;
            int4 z = make_int4(0, 0, 0, 0);
            *(int4*)&g_nodeCnt[idx0] = z;
        } else {
            if (idx0 + 0 < Nn) { c0 = g_nodeCnt[idx0 + 0]; g_nodeCnt[idx0 + 0] = 0; }
            if (idx0 + 1 < Nn) { c1 = g_nodeCnt[idx0 + 1]; g_nodeCnt[idx0 + 1] = 0; }
            if (idx0 + 2 < Nn) { c2 = g_nodeCnt[idx0 + 2]; g_nodeCnt[idx0 + 2] = 0; }
            if (idx0 + 3 < Nn) { c3 = g_nodeCnt[idx0 + 3]; g_nodeCnt[idx0 + 3] = 0; }
        }
        int s = c0 + c1 + c2 + c3;
        int v = s;
        for (int d = 1; d < 32; d <<= 1) {
            int u = __shfl_up_sync(~0u, v, d);
            if (lane >= d) v += u;
        }
        if (lane == 31) warpSum[w] = v;
        __syncthreads();
        if (w == 0) {
            int x = warpSum[lane];
            for (int d = 1; d < 32; d <<= 1) {
                int u = __shfl_up_sync(~0u, x, d);
                if (lane >= d) x += u;
            }
            warpSum[lane] = x;
        }
        __syncthreads();
        int warpExcl = w ? warpSum[w - 1] : 0;
        int run = s_carry + warpExcl + (v - s);
        if (idx0 + 0 < Nn) { g_nodeOff[idx0 + 0] = run; g_cursorN[idx0 + 0] = run; run += c0; }
        if (idx0 + 1 < Nn) { g_nodeOff[idx0 + 1] = run; g_cursorN[idx0 + 1] = run; run += c1; }
        if (idx0 + 2 < Nn) { g_nodeOff[idx0 + 2] = run; g_cursorN[idx0 + 2] = run; run += c2; }
        if (idx0 + 3 < Nn) { g_nodeOff[idx0 + 3] = run; g_cursorN[idx0 + 3] = run; run += c3; }
        __syncthreads();
        if (t == 0) s_carry += warpSum[31];
        __syncthreads();
    }
    if (t < NGRAPH) {
        int lo = 0, hi = Nn;
        while (lo < hi) {
            int mid = (lo + hi) >> 1;
            long long bv = b64 ? ((const long long*)bt_raw)[mid]
                               : (long long)((const int*)bt_raw)[mid];
            if (bv < (long long)t) lo = mid + 1; else hi = mid;
        }
        g_off[t] = (lo < Nn) ? g_nodeOff[lo] : E;
    }
    if (t == 0) g_off[NGRAPH] = E;
}

// ---------------- K3: scatter (blocks 0..nS-1) + P/Q MMA (rest) --------------
__global__ void __launch_bounds__(256) k_sp(const void* __restrict__ bt_raw,
                                            const float* __restrict__ emb,
                                            int E, int Nn, int nS) {
    __shared__ uint32_t Ah[128 * 20];
    __shared__ uint32_t Al[128 * 20];
    __shared__ uint32_t Bh[64 * 20];
    __shared__ uint32_t Bl[64 * 20];
    int tid = threadIdx.x;
    if ((int)blockIdx.x < nS) {
        int e = blockIdx.x * 256 + tid;
        if (e >= E) return;
        int ci = g_col[e];
        int pos = atomicAdd(&g_cursorN[ci], 1);
        bool b64 = (g_is64_bt != 0);
        int sg = b64 ? (int)((const long long*)bt_raw)[ci]
                     : ((const int*)bt_raw)[ci];
        sg = min(max(sg, 0), NGRAPH - 1);
        g_perm[pos] = e;
        g_colS[pos] = ci;
        g_rowS[pos] = g_row[e];
        g_segS[pos] = sg;
        return;
    }
    int idx = blockIdx.x - nS;
    int m0  = (idx >> 3) * 128;
    int nb  = (idx >> 1) & 3;
    int z   = idx & 1;
    int w = tid >> 5, lane = tid & 31, gq = lane >> 2, tig = lane & 3;

    float acc[8][4];
#pragma unroll
    for (int i = 0; i < 8; i++)
#pragma unroll
        for (int j = 0; j < 4; j++) acc[i][j] = 0.f;

    int rA   = tid >> 1;
    int half = tid & 1;
    int node = min(m0 + rA, Nn - 1);
    const uint32_t* w1h = &g_W1ph[(size_t)((z * 4 + nb) * 2) * 1024];
    const uint32_t* w1l = &g_W1pl[(size_t)((z * 4 + nb) * 2) * 1024];

    for (int kc = 0; kc < 2; kc++) {
        {
            const float* er = &emb[(size_t)node * 64 + kc * 32 + half * 16];
#pragma unroll
            for (int q = 0; q < 4; q++) {
                float4 v = *(const float4*)(er + q * 4);
                float h0, l0, h1, l1, h2, l2, h3, l3;
                bsplit(v.x, h0, l0); bsplit(v.y, h1, l1);
                bsplit(v.z, h2, l2); bsplit(v.w, h3, l3);
                int o = rA * 20 + half * 8 + q * 2;
                Ah[o]     = pkbf(h0, h1);
                Ah[o + 1] = pkbf(h2, h3);
                Al[o]     = pkbf(l0, l1);
                Al[o + 1] = pkbf(l2, l3);
            }
        }
#pragma unroll
        for (int i = tid; i < 1024; i += 256) {
            int n = i >> 4, k2 = i & 15;
            Bh[n * 20 + k2] = w1h[kc * 1024 + i];
            Bl[n * 20 + k2] = w1l[kc * 1024 + i];
        }
        __syncthreads();
        int r0 = w * 16;
#pragma unroll
        for (int ks = 0; ks < 2; ks++) {
            int kb = ks * 8;
            uint32_t ah0 = Ah[(r0 + gq) * 20 + kb + tig];
            uint32_t ah1 = Ah[(r0 + gq + 8) * 20 + kb + tig];
            uint32_t ah2 = Ah[(r0 + gq) * 20 + kb + tig + 4];
            uint32_t ah3 = Ah[(r0 + gq + 8) * 20 + kb + tig + 4];
            uint32_t al0 = Al[(r0 + gq) * 20 + kb + tig];
            uint32_t al1 = Al[(r0 + gq + 8) * 20 + kb + tig];
            uint32_t al2 = Al[(r0 + gq) * 20 + kb + tig + 4];
            uint32_t al3 = Al[(r0 + gq + 8) * 20 + kb + tig + 4];
#pragma unroll
            for (int nt = 0; nt < 8; nt++) {
                int nrow = nt * 8 + gq;
                uint32_t bh0 = Bh[nrow * 20 + kb + tig];
                uint32_t bh1 = Bh[nrow * 20 + kb + tig + 4];
                uint32_t bl0 = Bl[nrow * 20 + kb + tig];
                uint32_t bl1 = Bl[nrow * 20 + kb + tig + 4];
                mma16816(acc[nt], ah0, ah1, ah2, ah3, bh0, bh1);
                mma16816(acc[nt], ah0, ah1, ah2, ah3, bl0, bl1);
                mma16816(acc[nt], al0, al1, al2, al3, bh0, bh1);
            }
        }
        __syncthreads();
    }
    float*    dst  = z ? g_Q : g_P;
    uint32_t* dstb = z ? g_Qb : g_Pb;
    int row0 = m0 + w * 16 + gq;
    int row1 = row0 + 8;
#pragma unroll
    for (int nt = 0; nt < 8; nt++) {
        int cidx = nb * 64 + nt * 8 + tig * 2;
        if (row0 < Nn) {
            *(float2*)&dst[(size_t)row0 * 256 + cidx] = make_float2(acc[nt][0], acc[nt][1]);
            dstb[(size_t)row0 * 128 + (cidx >> 1)] = pkbf(acc[nt][0], acc[nt][1]);
        }
        if (row1 < Nn) {
            *(float2*)&dst[(size_t)row1 * 256 + cidx] = make_float2(acc[nt][2], acc[nt][3]);
            dstb[(size_t)row1 * 128 + (cidx >> 1)] = pkbf(acc[nt][2], acc[nt][3]);
        }
    }
}

// ---------------- K4: stats1 accumulate (edge-split, atomics; profiled) -------
// grid (128, 4, SPLIT1); block 256 = 8 warps; 64 channels per block.
__global__ void k_stats1a() {
    int g   = blockIdx.x;
    int c0u = blockIdx.y * 32;
    int zs  = blockIdx.z;
    int lane = threadIdx.x & 31, w = threadIdx.x >> 5;
    int start = g_off[g], end = g_off[g + 1];
    int len   = end - start;
    int chunk = (len + SPLIT1 - 1) / SPLIT1;
    int s0 = start + zs * chunk;
    int s1e = min(s0 + chunk, end);
    float s1a = 0.f, s1b = 0.f, s2a = 0.f, s2b = 0.f;
    int m = s0 + w;
    for (; m + 8 < s1e; m += 16) {
        uint32_t pu0 = g_Pb[(size_t)g_colS[m] * 128 + c0u + lane];
        uint32_t qu0 = g_Qb[(size_t)g_rowS[m] * 128 + c0u + lane];
        uint32_t pu1 = g_Pb[(size_t)g_colS[m + 8] * 128 + c0u + lane];
        uint32_t qu1 = g_Qb[(size_t)g_rowS[m + 8] * 128 + c0u + lane];
        float2 p0 = upbf(pu0), q0 = upbf(qu0);
        float2 p1 = upbf(pu1), q1 = upbf(qu1);
        float va0 = p0.x + q0.x, vb0 = p0.y + q0.y;
        float va1 = p1.x + q1.x, vb1 = p1.y + q1.y;
        s1a += va0 + va1; s2a += va0 * va0 + va1 * va1;
        s1b += vb0 + vb1; s2b += vb0 * vb0 + vb1 * vb1;
    }
    if (m < s1e) {
        uint32_t pu = g_Pb[(size_t)g_colS[m] * 128 + c0u + lane];
        uint32_t qu = g_Qb[(size_t)g_rowS[m] * 128 + c0u + lane];
        float2 p = upbf(pu), q = upbf(qu);
        float va = p.x + q.x, vb = p.y + q.y;
        s1a += va; s2a += va * va;
        s1b += vb; s2b += vb * vb;
    }
    __shared__ float r1a[8][32], r1b[8][32], r2a[8][32], r2b[8][32];
    r1a[w][lane] = s1a; r1b[w][lane] = s1b;
    r2a[w][lane] = s2a; r2b[w][lane] = s2b;
    __syncthreads();
    if (w == 0) {
#pragma unroll
        for (int t = 1; t < 8; t++) {
            s1a += r1a[t][lane]; s1b += r1b[t][lane];
            s2a += r2a[t][lane]; s2b += r2b[t][lane];
        }
        int ch = (c0u + lane) * 2;
        atomicAdd(&g_acc[g * 256 + ch],             s1a);
        atomicAdd(&g_acc[g * 256 + ch + 1],         s1b);
        atomicAdd(&g_acc[32768 + g * 256 + ch],     s2a);
        atomicAdd(&g_acc[32768 + g * 256 + ch + 1], s2b);
    }
}

// ---------------- K5: finalize mean1/rstd1 ------------------------------------
__global__ void k_fin1() {
    int g = blockIdx.x, ch = threadIdx.x;      // 128 x 256
    int cnti = g_off[g + 1] - g_off[g]; if (cnti < 1) cnti = 1;
    float inv = 1.f / (float)cnti;
    float mean = g_acc[g * 256 + ch] * inv;
    float var  = fmaxf(g_acc[32768 + g * 256 + ch] * inv - mean * mean, 0.f);
    g_mean1[g * 256 + ch] = mean;
    g_rstd1[g * 256 + ch] = rsqrtf(var + EPS);
}

// ---------------- K6: h2 via direct-load bf16 3-term MMA ----------------------
__global__ void __launch_bounds__(256) k_gemm2(int E) {
    __shared__ uint32_t Ah[128 * 20];
    __shared__ uint32_t Al[128 * 20];
    __shared__ uint32_t Bh[64 * 20];
    __shared__ uint32_t Bl[64 * 20];
    __shared__ int cS[128], rS[128], sS[128];
    int tid = threadIdx.x;
    int m0  = blockIdx.x * 128;
    int w = tid >> 5, lane = tid & 31, gq = lane >> 2, tig = lane & 3;
    if (tid < 128) {
        int m = m0 + tid; if (m >= E) m = E - 1;
        cS[tid] = g_colS[m]; rS[tid] = g_rowS[m]; sS[tid] = g_segS[m];
    }
    __syncthreads();

    float acc[8][4];
#pragma unroll
    for (int i = 0; i < 8; i++)
#pragma unroll
        for (int j = 0; j < 4; j++) acc[i][j] = 0.f;

    int rA   = tid >> 1;
    int half = tid & 1;
    int cA = cS[rA], rB = rS[rA], sgA = sS[rA];

    for (int kc = 0; kc < 8; kc++) {
        {
            int kb = kc * 32 + half * 16;
            const float* pB  = &g_P[(size_t)cA * 256 + kb];
            const float* qB  = &g_Q[(size_t)rB * 256 + kb];
            const float* muB = &g_mean1[sgA * 256 + kb];
            const float* rsB = &g_rstd1[sgA * 256 + kb];
#pragma unroll
            for (int q = 0; q < 4; q++) {
                float4 p  = *(const float4*)(pB + q * 4);
                float4 qv = *(const float4*)(qB + q * 4);
                float4 mu = *(const float4*)(muB + q * 4);
                float4 rs = *(const float4*)(rsB + q * 4);
                float v0 = fmaxf((p.x + qv.x - mu.x) * rs.x, 0.f);
                float v1 = fmaxf((p.y + qv.y - mu.y) * rs.y, 0.f);
                float v2 = fmaxf((p.z + qv.z - mu.z) * rs.z, 0.f);
                float v3 = fmaxf((p.w + qv.w - mu.w) * rs.w, 0.f);
                float h0, l0, h1, l1, h2, l2, h3, l3;
                bsplit(v0, h0, l0); bsplit(v1, h1, l1);
                bsplit(v2, h2, l2); bsplit(v3, h3, l3);
                int o = rA * 20 + half * 8 + q * 2;
                Ah[o]     = pkbf(h0, h1);
                Ah[o + 1] = pkbf(h2, h3);
                Al[o]     = pkbf(l0, l1);
                Al[o + 1] = pkbf(l2, l3);
            }
        }
#pragma unroll
        for (int i = tid; i < 1024; i += 256) {
            int n = i >> 4, k2 = i & 15;
            Bh[n * 20 + k2] = g_W2ph[kc * 1024 + i];
            Bl[n * 20 + k2] = g_W2pl[kc * 1024 + i];
        }
        __syncthreads();
        int r0 = w * 16;
#pragma unroll
        for (int ks = 0; ks < 2; ks++) {
            int kb = ks * 8;
            uint32_t ah0 = Ah[(r0 + gq) * 20 + kb + tig];
            uint32_t ah1 = Ah[(r0 + gq + 8) * 20 + kb + tig];
            uint32_t ah2 = Ah[(r0 + gq) * 20 + kb + tig + 4];
            uint32_t ah3 = Ah[(r0 + gq + 8) * 20 + kb + tig + 4];
            uint32_t al0 = Al[(r0 + gq) * 20 + kb + tig];
            uint32_t al1 = Al[(r0 + gq + 8) * 20 + kb + tig];
            uint32_t al2 = Al[(r0 + gq) * 20 + kb + tig + 4];
            uint32_t al3 = Al[(r0 + gq + 8) * 20 + kb + tig + 4];
#pragma unroll
            for (int nt = 0; nt < 8; nt++) {
                int nrow = nt * 8 + gq;
                uint32_t bh0 = Bh[nrow * 20 + kb + tig];
                uint32_t bh1 = Bh[nrow * 20 + kb + tig + 4];
                uint32_t bl0 = Bl[nrow * 20 + kb + tig];
                uint32_t bl1 = Bl[nrow * 20 + kb + tig + 4];
                mma16816(acc[nt], ah0, ah1, ah2, ah3, bh0, bh1);
                mma16816(acc[nt], ah0, ah1, ah2, ah3, bl0, bl1);
                mma16816(acc[nt], al0, al1, al2, al3, bh0, bh1);
            }
        }
        __syncthreads();
    }
    int row0 = m0 + w * 16 + gq;
    int row1 = row0 + 8;
#pragma unroll
    for (int nt = 0; nt < 8; nt++) {
        int cidx = nt * 8 + tig * 2;
        if (row0 < E)
            __stcs((float2*)&g_h2[(size_t)row0 * 64 + cidx],
                   make_float2(acc[nt][0], acc[nt][1]));
        if (row1 < E)
            __stcs((float2*)&g_h2[(size_t)row1 * 64 + cidx],
                   make_float2(acc[nt][2], acc[nt][3]));
    }
}

// ---------------- K7: stats2 accumulate (edge-split, atomics) ------------------
// grid (128, 2, SPLIT2); block 256 = 8 warps; 32 channels per block.
__global__ void k_stats2a() {
    int g  = blockIdx.x;
    int c0 = blockIdx.y * 32;
    int zs = blockIdx.z;
    int lane = threadIdx.x & 31, w = threadIdx.x >> 5;
    int start = g_off[g], end = g_off[g + 1];
    int len   = end - start;
    int chunk = (len + SPLIT2 - 1) / SPLIT2;
    int s0 = start + zs * chunk;
    int s1e = min(s0 + chunk, end);
    int ch = c0 + lane;
    float s1 = 0.f, s2 = 0.f;
    int m = s0 + w;
    for (; m + 8 < s1e; m += 16) {
        float va = g_h2[(size_t)m * 64 + ch];
        float vb = g_h2[(size_t)(m + 8) * 64 + ch];
        s1 += va + vb; s2 += va * va + vb * vb;
    }
    if (m < s1e) {
        float v = g_h2[(size_t)m * 64 + ch];
        s1 += v; s2 += v * v;
    }
    __shared__ float a1[8][32], a2[8][32];
    a1[w][lane] = s1; a2[w][lane] = s2;
    __syncthreads();
    if (w == 0) {
#pragma unroll
        for (int t = 1; t < 8; t++) { s1 += a1[t][lane]; s2 += a2[t][lane]; }
        atomicAdd(&g_acc[65536 + g * 64 + ch], s1);
        atomicAdd(&g_acc[73728 + g * 64 + ch], s2);
    }
}

// ---------------- K8: finalize mean2/rstd2 --------------------------------------
__global__ void k_fin2() {
    int g = blockIdx.x, ch = threadIdx.x;      // 128 x 64
    int cnti = g_off[g + 1] - g_off[g]; if (cnti < 1) cnti = 1;
    float inv = 1.f / (float)cnti;
    float mean = g_acc[65536 + g * 64 + ch] * inv;
    float var  = fmaxf(g_acc[73728 + g * 64 + ch] * inv - mean * mean, 0.f);
    g_mean2[g * 64 + ch] = mean;
    g_rstd2[g * 64 + ch] = rsqrtf(var + EPS);
}

// ---------------- K9: out[perm[m]] = relu(norm2(h2)) . W3 + b3 -----------------
__global__ void k_final(const float* __restrict__ W3,
                        const float* __restrict__ b3,
                        float* __restrict__ out, int E) {
    __shared__ __align__(16) float sm[128 * 65];
    __shared__ float w3s[64];
    __shared__ int   sS[128];
    int tid = threadIdx.x;   // 128
    int m0  = blockIdx.x * 128;
    if (tid < 64) w3s[tid] = W3[tid];
    {
        int m = m0 + tid; if (m >= E) m = E - 1;
        sS[tid] = g_segS[m];
    }
    __syncthreads();
#pragma unroll
    for (int t = tid; t < 128 * 16; t += 128) {
        int rr = t >> 4, q = t & 15;
        int m = m0 + rr; if (m >= E) m = E - 1;
        float4 v  = __ldcs((const float4*)&g_h2[(size_t)m * 64 + q * 4]);
        int s = sS[rr];
        float4 mu = *(const float4*)&g_mean2[s * 64 + q * 4];
        float4 rs = *(const float4*)&g_rstd2[s * 64 + q * 4];
        float* d = &sm[rr * 65 + q * 4];
        d[0] = fmaxf((v.x - mu.x) * rs.x, 0.f);
        d[1] = fmaxf((v.y - mu.y) * rs.y, 0.f);
        d[2] = fmaxf((v.z - mu.z) * rs.z, 0.f);
        d[3] = fmaxf((v.w - mu.w) * rs.w, 0.f);
    }
    __syncthreads();
    int m = m0 + tid;
    if (m < E) {
        float acc = 0.f;
#pragma unroll
        for (int k = 0; k < 64; k++) acc += sm[tid * 65 + k] * w3s[k];
        out[g_perm[m]] = acc + b3[0];
    }
}

// ---------------- launch ---------------------------------------------------------
extern "C" void kernel_launch(void* const* d_in, const int* in_sizes, int n_in,
                              void* d_out, int out_size) {
    const float* emb = (const float*)d_in[0];
    const void*  ei  = d_in[1];
    const void*  bt  = d_in[2];
    const float* W1  = (const float*)d_in[3];
    // d_in[4] = b1 : cancels exactly through affine-free InstanceNorm
    const float* W2  = (const float*)d_in[5];
    // d_in[6] = b2 : cancels exactly through affine-free InstanceNorm
    const float* W3  = (const float*)d_in[7];
    const float* b3  = (const float*)d_in[8];
    float* out = (float*)d_out;

    int Nn = in_sizes[0] / 64;
    int E  = in_sizes[1] / 2;

    int nEdgeBlk = (E + 255) / 256;
    int nPqBlk   = ((Nn + 127) / 128) * 8;

    k_prep<<<176 + nEdgeBlk, 256>>>(ei, W1, W2, E, Nn);          // 1
    k_scan_node<<<1, 1024>>>(bt, E, Nn);                         // 2
    k_sp<<<nEdgeBlk + nPqBlk, 256>>>(bt, emb, E, Nn, nEdgeBlk);  // 3
    k_stats1a<<<dim3(128, 4, SPLIT1), 256>>>();                  // 4 (profiled)
    k_fin1<<<128, 256>>>();                                      // 5
    k_gemm2<<<(E + 127) / 128, 256>>>(E);                        // 6
    k_stats2a<<<dim3(128, 2, SPLIT2), 256>>>();                  // 7
    k_fin2<<<128, 64>>>();                                       // 8
    k_final<<<(E + 127) / 128, 128>>>(W3, b3, out, E);           // 9
}

// round 10
// speedup vs baseline: 1.4736x; 1.0181x over previous
#include <cuda_runtime.h>
#include <cuda_bf16.h>
#include <cstdint>

#define EPS 1e-5f
#define NGRAPH 128
#define EMAX 800000
#define NMAX 50000
#define SPLIT1 8
#define SPLIT2 16

// ---------------- scratch (__device__ globals; no allocation allowed) -------
__device__ int g_is64_bt;
__device__ int g_nodeCnt[NMAX];
__device__ int g_nodeOff[NMAX];
__device__ int g_cursorN[NMAX];
__device__ int g_off[NGRAPH + 1];
__device__ int g_col[EMAX];
__device__ int g_row[EMAX];
__device__ int g_perm[EMAX];
__device__ int g_segS[EMAX];
__device__ int g_colS[EMAX];
__device__ int g_rowS[EMAX];
__device__ __align__(16) float g_P[NMAX * 256];
__device__ __align__(16) float g_Q[NMAX * 256];
__device__ __align__(16) uint32_t g_Pb[NMAX * 128];  // bf16x2 copy of P
__device__ __align__(16) uint32_t g_Qb[NMAX * 128];  // bf16x2 copy of Q
__device__ __align__(16) float g_h2[(size_t)EMAX * 64];
__device__ __align__(16) float g_mean1[NGRAPH * 256];
__device__ __align__(16) float g_rstd1[NGRAPH * 256];
__device__ __align__(16) float g_mean2[NGRAPH * 64];
__device__ __align__(16) float g_rstd2[NGRAPH * 64];
// accumulators: s1[32768] s2[32768] t1[8192] t2[8192]
__device__ __align__(16) float g_acc[81920];
// W2 pre-split bf16 hi/lo packed b32: [kc 8][n 64][k2 16]
__device__ __align__(16) uint32_t g_W2ph[8192];
__device__ __align__(16) uint32_t g_W2pl[8192];
// W1 pre-split bf16 hi/lo packed b32: [z 2][nb 4][kc 2][n 64][k2 16]
__device__ __align__(16) uint32_t g_W1ph[16384];
__device__ __align__(16) uint32_t g_W1pl[16384];

// ---------------- helpers ----------------------------------------------------
__device__ __forceinline__ uint32_t pkbf(float a, float b) {
    __nv_bfloat162 h = __floats2bfloat162_rn(a, b);
    return *(uint32_t*)&h;
}
__device__ __forceinline__ float2 upbf(uint32_t u) {
    __nv_bfloat162 h = *(__nv_bfloat162*)&u;
    return make_float2(__bfloat162float(h.x), __bfloat162float(h.y));
}
__device__ __forceinline__ void bsplit(float v, float& hi, float& lo) {
    __nv_bfloat16 h = __float2bfloat16(v);
    hi = __bfloat162float(h);
    lo = v - hi;
}
__device__ __forceinline__ void mma16816(float* c, uint32_t a0, uint32_t a1,
                                         uint32_t a2, uint32_t a3,
                                         uint32_t b0, uint32_t b1) {
    asm volatile(
        "mma.sync.aligned.m16n8k16.row.col.f32.bf16.bf16.f32 "
        "{%0,%1,%2,%3}, {%4,%5,%6,%7}, {%8,%9}, {%0,%1,%2,%3};"
        : "+f"(c[0]), "+f"(c[1]), "+f"(c[2]), "+f"(c[3])
        : "r"(a0), "r"(a1), "r"(a2), "r"(a3), "r"(b0), "r"(b1));
}

// ---------------- K1: prep = W split | acc zero | edge decode ----------------
__global__ void k_prep(const void* __restrict__ ei_raw,
                       const float* __restrict__ W1,
                       const float* __restrict__ W2, int E, int Nn) {
    int bid = blockIdx.x;
    int t = threadIdx.x;               // 256
    if (bid < 96) {
        int i = bid * 256 + t;
        if (i < 16384) {
            int z  = i >> 13;
            int nb = (i >> 11) & 3;
            int kc = (i >> 10) & 1;
            int n  = (i >> 4) & 63;
            int k2 = i & 15;
            int kk  = z * 64 + kc * 32 + k2 * 2;
            int col = nb * 64 + n;
            float wa = W1[kk * 256 + col];
            float wb = W1[(kk + 1) * 256 + col];
            float ha, la, hb, lb;
            bsplit(wa, ha, la); bsplit(wb, hb, lb);
            g_W1ph[i] = pkbf(ha, hb);
            g_W1pl[i] = pkbf(la, lb);
        } else {
            int j = i - 16384;
            int kc = j >> 10, n = (j >> 4) & 63, k2 = j & 15;
            int kk = kc * 32 + k2 * 2;
            float wa = W2[kk * 64 + n];
            float wb = W2[(kk + 1) * 64 + n];
            float ha, la, hb, lb;
            bsplit(wa, ha, la); bsplit(wb, hb, lb);
            g_W2ph[j] = pkbf(ha, hb);
            g_W2pl[j] = pkbf(la, lb);
        }
        return;
    }
    if (bid < 176) {                    // zero 81920 floats = 20480 float4
        int i = (bid - 96) * 256 + t;
        *(float4*)&g_acc[i * 4] = make_float4(0.f, 0.f, 0.f, 0.f);
        return;
    }
    // edge decode + node histogram
    __shared__ int s_nz;
    if (t == 0) s_nz = 0;
    __syncthreads();
    const int* ei32 = (const int*)ei_raw;
    if (ei32[2 * t + 1]) atomicOr(&s_nz, 1);
    __syncthreads();
    bool e64 = (s_nz == 0);
    int e = (bid - 176) * 256 + t;
    if (e >= E) return;
    int ci, ri;
    if (e64) {
        ci = (int)((const long long*)ei_raw)[e];
        ri = (int)((const long long*)ei_raw)[(size_t)E + e];
    } else {
        ci = ei32[e];
        ri = ei32[E + e];
    }
    ci = min(max(ci, 0), Nn - 1);
    ri = min(max(ri, 0), Nn - 1);
    g_col[e] = ci; g_row[e] = ri;
    atomicAdd(&g_nodeCnt[ci], 1);
}

// ---------------- K2: tile-scan (self-clearing) + graph offsets + bt detect ---
__global__ void k_scan_node(const void* __restrict__ bt_raw, int E, int Nn) {
    __shared__ int warpSum[32];
    __shared__ int s_bt, s_carry;
    int t = threadIdx.x;               // 1024
    int lane = t & 31, w = t >> 5;
    if (t == 0) { s_bt = 0; s_carry = 0; }
    __syncthreads();
    {
        const int* bt32 = (const int*)bt_raw;
        int lim = Nn / 2 < 16384 ? Nn / 2 : 16384;
        int nz = 0;
        for (int i = t; i < lim; i += 1024) nz |= bt32[2 * i + 1];
        for (int d = 16; d; d >>= 1) nz |= __shfl_xor_sync(~0u, nz, d);
        if (lane == 0 && nz) atomicOr(&s_bt, 1);
    }
    __syncthreads();
    bool b64 = (s_bt == 0);
    if (t == 0) g_is64_bt = b64 ? 1 : 0;

    int ntile = (Nn + 4095) >> 12;
    for (int tile = 0; tile < ntile; tile++) {
        int idx0 = (tile << 12) + t * 4;
        int c0 = 0, c1 = 0, c2 = 0, c3 = 0;
        if (idx0 + 3 < Nn) {
            int4 c = *(const int4*)&g_nodeCnt[idx0];
            c0 = c.x; c1 = c.y; c2 = c.z; c3 = c.w;
            int4 z = make_int4(0, 0, 0, 0);
            *(int4*)&g_nodeCnt[idx0] = z;
        } else {
            if (idx0 + 0 < Nn) { c0 = g_nodeCnt[idx0 + 0]; g_nodeCnt[idx0 + 0] = 0; }
            if (idx0 + 1 < Nn) { c1 = g_nodeCnt[idx0 + 1]; g_nodeCnt[idx0 + 1] = 0; }
            if (idx0 + 2 < Nn) { c2 = g_nodeCnt[idx0 + 2]; g_nodeCnt[idx0 + 2] = 0; }
            if (idx0 + 3 < Nn) { c3 = g_nodeCnt[idx0 + 3]; g_nodeCnt[idx0 + 3] = 0; }
        }
        int s = c0 + c1 + c2 + c3;
        int v = s;
        for (int d = 1; d < 32; d <<= 1) {
            int u = __shfl_up_sync(~0u, v, d);
            if (lane >= d) v += u;
        }
        if (lane == 31) warpSum[w] = v;
        __syncthreads();
        if (w == 0) {
            int x = warpSum[lane];
            for (int d = 1; d < 32; d <<= 1) {
                int u = __shfl_up_sync(~0u, x, d);
                if (lane >= d) x += u;
            }
            warpSum[lane] = x;
        }
        __syncthreads();
        int warpExcl = w ? warpSum[w - 1] : 0;
        int run = s_carry + warpExcl + (v - s);
        if (idx0 + 0 < Nn) { g_nodeOff[idx0 + 0] = run; g_cursorN[idx0 + 0] = run; run += c0; }
        if (idx0 + 1 < Nn) { g_nodeOff[idx0 + 1] = run; g_cursorN[idx0 + 1] = run; run += c1; }
        if (idx0 + 2 < Nn) { g_nodeOff[idx0 + 2] = run; g_cursorN[idx0 + 2] = run; run += c2; }
        if (idx0 + 3 < Nn) { g_nodeOff[idx0 + 3] = run; g_cursorN[idx0 + 3] = run; run += c3; }
        __syncthreads();
        if (t == 0) s_carry += warpSum[31];
        __syncthreads();
    }
    if (t < NGRAPH) {
        int lo = 0, hi = Nn;
        while (lo < hi) {
            int mid = (lo + hi) >> 1;
            long long bv = b64 ? ((const long long*)bt_raw)[mid]
                               : (long long)((const int*)bt_raw)[mid];
            if (bv < (long long)t) lo = mid + 1; else hi = mid;
        }
        g_off[t] = (lo < Nn) ? g_nodeOff[lo] : E;
    }
    if (t == 0) g_off[NGRAPH] = E;
}

// ---------------- K3: scatter (blocks 0..nS-1) + P/Q MMA (rest) --------------
__global__ void __launch_bounds__(256) k_sp(const void* __restrict__ bt_raw,
                                            const float* __restrict__ emb,
                                            int E, int Nn, int nS) {
    __shared__ uint32_t Ah[128 * 20];
    __shared__ uint32_t Al[128 * 20];
    __shared__ uint32_t Bh[64 * 20];
    __shared__ uint32_t Bl[64 * 20];
    int tid = threadIdx.x;
    if ((int)blockIdx.x < nS) {
        int e = blockIdx.x * 256 + tid;
        if (e >= E) return;
        int ci = g_col[e];
        int pos = atomicAdd(&g_cursorN[ci], 1);
        bool b64 = (g_is64_bt != 0);
        int sg = b64 ? (int)((const long long*)bt_raw)[ci]
                     : ((const int*)bt_raw)[ci];
        sg = min(max(sg, 0), NGRAPH - 1);
        g_perm[pos] = e;
        g_colS[pos] = ci;
        g_rowS[pos] = g_row[e];
        g_segS[pos] = sg;
        return;
    }
    int idx = blockIdx.x - nS;
    int m0  = (idx >> 3) * 128;
    int nb  = (idx >> 1) & 3;
    int z   = idx & 1;
    int w = tid >> 5, lane = tid & 31, gq = lane >> 2, tig = lane & 3;

    float acc[8][4];
#pragma unroll
    for (int i = 0; i < 8; i++)
#pragma unroll
        for (int j = 0; j < 4; j++) acc[i][j] = 0.f;

    int rA   = tid >> 1;
    int half = tid & 1;
    int node = min(m0 + rA, Nn - 1);
    const uint32_t* w1h = &g_W1ph[(size_t)((z * 4 + nb) * 2) * 1024];
    const uint32_t* w1l = &g_W1pl[(size_t)((z * 4 + nb) * 2) * 1024];

    for (int kc = 0; kc < 2; kc++) {
        {
            const float* er = &emb[(size_t)node * 64 + kc * 32 + half * 16];
#pragma unroll
            for (int q = 0; q < 4; q++) {
                float4 v = *(const float4*)(er + q * 4);
                float h0, l0, h1, l1, h2, l2, h3, l3;
                bsplit(v.x, h0, l0); bsplit(v.y, h1, l1);
                bsplit(v.z, h2, l2); bsplit(v.w, h3, l3);
                int o = rA * 20 + half * 8 + q * 2;
                Ah[o]     = pkbf(h0, h1);
                Ah[o + 1] = pkbf(h2, h3);
                Al[o]     = pkbf(l0, l1);
                Al[o + 1] = pkbf(l2, l3);
            }
        }
#pragma unroll
        for (int i = tid; i < 1024; i += 256) {
            int n = i >> 4, k2 = i & 15;
            Bh[n * 20 + k2] = w1h[kc * 1024 + i];
            Bl[n * 20 + k2] = w1l[kc * 1024 + i];
        }
        __syncthreads();
        int r0 = w * 16;
#pragma unroll
        for (int ks = 0; ks < 2; ks++) {
            int kb = ks * 8;
            uint32_t ah0 = Ah[(r0 + gq) * 20 + kb + tig];
            uint32_t ah1 = Ah[(r0 + gq + 8) * 20 + kb + tig];
            uint32_t ah2 = Ah[(r0 + gq) * 20 + kb + tig + 4];
            uint32_t ah3 = Ah[(r0 + gq + 8) * 20 + kb + tig + 4];
            uint32_t al0 = Al[(r0 + gq) * 20 + kb + tig];
            uint32_t al1 = Al[(r0 + gq + 8) * 20 + kb + tig];
            uint32_t al2 = Al[(r0 + gq) * 20 + kb + tig + 4];
            uint32_t al3 = Al[(r0 + gq + 8) * 20 + kb + tig + 4];
#pragma unroll
            for (int nt = 0; nt < 8; nt++) {
                int nrow = nt * 8 + gq;
                uint32_t bh0 = Bh[nrow * 20 + kb + tig];
                uint32_t bh1 = Bh[nrow * 20 + kb + tig + 4];
                uint32_t bl0 = Bl[nrow * 20 + kb + tig];
                uint32_t bl1 = Bl[nrow * 20 + kb + tig + 4];
                mma16816(acc[nt], ah0, ah1, ah2, ah3, bh0, bh1);
                mma16816(acc[nt], ah0, ah1, ah2, ah3, bl0, bl1);
                mma16816(acc[nt], al0, al1, al2, al3, bh0, bh1);
            }
        }
        __syncthreads();
    }
    float*    dst  = z ? g_Q : g_P;
    uint32_t* dstb = z ? g_Qb : g_Pb;
    int row0 = m0 + w * 16 + gq;
    int row1 = row0 + 8;
#pragma unroll
    for (int nt = 0; nt < 8; nt++) {
        int cidx = nb * 64 + nt * 8 + tig * 2;
        if (row0 < Nn) {
            *(float2*)&dst[(size_t)row0 * 256 + cidx] = make_float2(acc[nt][0], acc[nt][1]);
            dstb[(size_t)row0 * 128 + (cidx >> 1)] = pkbf(acc[nt][0], acc[nt][1]);
        }
        if (row1 < Nn) {
            *(float2*)&dst[(size_t)row1 * 256 + cidx] = make_float2(acc[nt][2], acc[nt][3]);
            dstb[(size_t)row1 * 128 + (cidx >> 1)] = pkbf(acc[nt][2], acc[nt][3]);
        }
    }
}

// ---------------- K4: stats1 accumulate (uint2 gathers; profiled) ------------
// grid (128, 2, SPLIT1); block 256 = 8 warps; lane covers 4 channels via uint2.
__global__ void k_stats1a() {
    int g    = blockIdx.x;
    int c0u  = blockIdx.y * 64;          // u32 base; lane handles idx, idx+1
    int zs   = blockIdx.z;
    int lane = threadIdx.x & 31, w = threadIdx.x >> 5;
    int idx  = c0u + lane * 2;
    int start = g_off[g], end = g_off[g + 1];
    int len   = end - start;
    int chunk = (len + SPLIT1 - 1) / SPLIT1;
    int s0  = start + zs * chunk;
    int s1e = min(s0 + chunk, end);
    float s1[4] = {0.f, 0.f, 0.f, 0.f};
    float s2[4] = {0.f, 0.f, 0.f, 0.f};
    int m = s0 + w;
    for (; m + 8 < s1e; m += 16) {
        uint2 pu0 = *(const uint2*)&g_Pb[(size_t)g_colS[m] * 128 + idx];
        uint2 qu0 = *(const uint2*)&g_Qb[(size_t)g_rowS[m] * 128 + idx];
        uint2 pu1 = *(const uint2*)&g_Pb[(size_t)g_colS[m + 8] * 128 + idx];
        uint2 qu1 = *(const uint2*)&g_Qb[(size_t)g_rowS[m + 8] * 128 + idx];
        float2 pa0 = upbf(pu0.x), pb0 = upbf(pu0.y);
        float2 qa0 = upbf(qu0.x), qb0 = upbf(qu0.y);
        float2 pa1 = upbf(pu1.x), pb1 = upbf(pu1.y);
        float2 qa1 = upbf(qu1.x), qb1 = upbf(qu1.y);
        float v00 = pa0.x + qa0.x, v01 = pa0.y + qa0.y;
        float v02 = pb0.x + qb0.x, v03 = pb0.y + qb0.y;
        float v10 = pa1.x + qa1.x, v11 = pa1.y + qa1.y;
        float v12 = pb1.x + qb1.x, v13 = pb1.y + qb1.y;
        s1[0] += v00 + v10; s2[0] += v00 * v00 + v10 * v10;
        s1[1] += v01 + v11; s2[1] += v01 * v01 + v11 * v11;
        s1[2] += v02 + v12; s2[2] += v02 * v02 + v12 * v12;
        s1[3] += v03 + v13; s2[3] += v03 * v03 + v13 * v13;
    }
    if (m < s1e) {
        uint2 pu = *(const uint2*)&g_Pb[(size_t)g_colS[m] * 128 + idx];
        uint2 qu = *(const uint2*)&g_Qb[(size_t)g_rowS[m] * 128 + idx];
        float2 pa = upbf(pu.x), pb = upbf(pu.y);
        float2 qa = upbf(qu.x), qb = upbf(qu.y);
        float v0 = pa.x + qa.x, v1 = pa.y + qa.y;
        float v2 = pb.x + qb.x, v3 = pb.y + qb.y;
        s1[0] += v0; s2[0] += v0 * v0;
        s1[1] += v1; s2[1] += v1 * v1;
        s1[2] += v2; s2[2] += v2 * v2;
        s1[3] += v3; s2[3] += v3 * v3;
    }
    __shared__ float r1[8][32][4], r2[8][32][4];
#pragma unroll
    for (int j = 0; j < 4; j++) { r1[w][lane][j] = s1[j]; r2[w][lane][j] = s2[j]; }
    __syncthreads();
    if (w == 0) {
#pragma unroll
        for (int t = 1; t < 8; t++)
#pragma unroll
            for (int j = 0; j < 4; j++) {
                s1[j] += r1[t][lane][j];
                s2[j] += r2[t][lane][j];
            }
        int ch = idx * 2;                 // channel base, covers ch..ch+3
#pragma unroll
        for (int j = 0; j < 4; j++) {
            atomicAdd(&g_acc[g * 256 + ch + j],         s1[j]);
            atomicAdd(&g_acc[32768 + g * 256 + ch + j], s2[j]);
        }
    }
}

// ---------------- K5: finalize mean1/rstd1 ------------------------------------
__global__ void k_fin1() {
    int g = blockIdx.x, ch = threadIdx.x;      // 128 x 256
    int cnti = g_off[g + 1] - g_off[g]; if (cnti < 1) cnti = 1;
    float inv = 1.f / (float)cnti;
    float mean = g_acc[g * 256 + ch] * inv;
    float var  = fmaxf(g_acc[32768 + g * 256 + ch] * inv - mean * mean, 0.f);
    g_mean1[g * 256 + ch] = mean;
    g_rstd1[g * 256 + ch] = rsqrtf(var + EPS);
}

// ---------------- K6: h2 via direct-load bf16 3-term MMA ----------------------
__global__ void __launch_bounds__(256) k_gemm2(int E) {
    __shared__ uint32_t Ah[128 * 20];
    __shared__ uint32_t Al[128 * 20];
    __shared__ uint32_t Bh[64 * 20];
    __shared__ uint32_t Bl[64 * 20];
    __shared__ int cS[128], rS[128], sS[128];
    int tid = threadIdx.x;
    int m0  = blockIdx.x * 128;
    int w = tid >> 5, lane = tid & 31, gq = lane >> 2, tig = lane & 3;
    if (tid < 128) {
        int m = m0 + tid; if (m >= E) m = E - 1;
        cS[tid] = g_colS[m]; rS[tid] = g_rowS[m]; sS[tid] = g_segS[m];
    }
    __syncthreads();

    float acc[8][4];
#pragma unroll
    for (int i = 0; i < 8; i++)
#pragma unroll
        for (int j = 0; j < 4; j++) acc[i][j] = 0.f;

    int rA   = tid >> 1;
    int half = tid & 1;
    int cA = cS[rA], rB = rS[rA], sgA = sS[rA];

    for (int kc = 0; kc < 8; kc++) {
        {
            int kb = kc * 32 + half * 16;
            const float* pB  = &g_P[(size_t)cA * 256 + kb];
            const float* qB  = &g_Q[(size_t)rB * 256 + kb];
            const float* muB = &g_mean1[sgA * 256 + kb];
            const float* rsB = &g_rstd1[sgA * 256 + kb];
#pragma unroll
            for (int q = 0; q < 4; q++) {
                float4 p  = *(const float4*)(pB + q * 4);
                float4 qv = *(const float4*)(qB + q * 4);
                float4 mu = *(const float4*)(muB + q * 4);
                float4 rs = *(const float4*)(rsB + q * 4);
                float v0 = fmaxf((p.x + qv.x - mu.x) * rs.x, 0.f);
                float v1 = fmaxf((p.y + qv.y - mu.y) * rs.y, 0.f);
                float v2 = fmaxf((p.z + qv.z - mu.z) * rs.z, 0.f);
                float v3 = fmaxf((p.w + qv.w - mu.w) * rs.w, 0.f);
                float h0, l0, h1, l1, h2, l2, h3, l3;
                bsplit(v0, h0, l0); bsplit(v1, h1, l1);
                bsplit(v2, h2, l2); bsplit(v3, h3, l3);
                int o = rA * 20 + half * 8 + q * 2;
                Ah[o]     = pkbf(h0, h1);
                Ah[o + 1] = pkbf(h2, h3);
                Al[o]     = pkbf(l0, l1);
                Al[o + 1] = pkbf(l2, l3);
            }
        }
#pragma unroll
        for (int i = tid; i < 1024; i += 256) {
            int n = i >> 4, k2 = i & 15;
            Bh[n * 20 + k2] = g_W2ph[kc * 1024 + i];
            Bl[n * 20 + k2] = g_W2pl[kc * 1024 + i];
        }
        __syncthreads();
        int r0 = w * 16;
#pragma unroll
        for (int ks = 0; ks < 2; ks++) {
            int kb = ks * 8;
            uint32_t ah0 = Ah[(r0 + gq) * 20 + kb + tig];
            uint32_t ah1 = Ah[(r0 + gq + 8) * 20 + kb + tig];
            uint32_t ah2 = Ah[(r0 + gq) * 20 + kb + tig + 4];
            uint32_t ah3 = Ah[(r0 + gq + 8) * 20 + kb + tig + 4];
            uint32_t al0 = Al[(r0 + gq) * 20 + kb + tig];
            uint32_t al1 = Al[(r0 + gq + 8) * 20 + kb + tig];
            uint32_t al2 = Al[(r0 + gq) * 20 + kb + tig + 4];
            uint32_t al3 = Al[(r0 + gq + 8) * 20 + kb + tig + 4];
#pragma unroll
            for (int nt = 0; nt < 8; nt++) {
                int nrow = nt * 8 + gq;
                uint32_t bh0 = Bh[nrow * 20 + kb + tig];
                uint32_t bh1 = Bh[nrow * 20 + kb + tig + 4];
                uint32_t bl0 = Bl[nrow * 20 + kb + tig];
                uint32_t bl1 = Bl[nrow * 20 + kb + tig + 4];
                mma16816(acc[nt], ah0, ah1, ah2, ah3, bh0, bh1);
                mma16816(acc[nt], ah0, ah1, ah2, ah3, bl0, bl1);
                mma16816(acc[nt], al0, al1, al2, al3, bh0, bh1);
            }
        }
        __syncthreads();
    }
    int row0 = m0 + w * 16 + gq;
    int row1 = row0 + 8;
#pragma unroll
    for (int nt = 0; nt < 8; nt++) {
        int cidx = nt * 8 + tig * 2;
        if (row0 < E)
            __stcs((float2*)&g_h2[(size_t)row0 * 64 + cidx],
                   make_float2(acc[nt][0], acc[nt][1]));
        if (row1 < E)
            __stcs((float2*)&g_h2[(size_t)row1 * 64 + cidx],
                   make_float2(acc[nt][2], acc[nt][3]));
    }
}

// ---------------- K7: stats2 accumulate (float2 loads, edge-split) ------------
// grid (128, SPLIT2); block 256 = 8 warps; lane covers 2 channels via float2.
__global__ void k_stats2a() {
    int g  = blockIdx.x;
    int zs = blockIdx.y;
    int lane = threadIdx.x & 31, w = threadIdx.x >> 5;
    int ch2 = lane * 2;
    int start = g_off[g], end = g_off[g + 1];
    int len   = end - start;
    int chunk = (len + SPLIT2 - 1) / SPLIT2;
    int s0  = start + zs * chunk;
    int s1e = min(s0 + chunk, end);
    float s1a = 0.f, s1b = 0.f, s2a = 0.f, s2b = 0.f;
    int m = s0 + w;
    for (; m + 8 < s1e; m += 16) {
        float2 v0 = *(const float2*)&g_h2[(size_t)m * 64 + ch2];
        float2 v1 = *(const float2*)&g_h2[(size_t)(m + 8) * 64 + ch2];
        s1a += v0.x + v1.x; s2a += v0.x * v0.x + v1.x * v1.x;
        s1b += v0.y + v1.y; s2b += v0.y * v0.y + v1.y * v1.y;
    }
    if (m < s1e) {
        float2 v = *(const float2*)&g_h2[(size_t)m * 64 + ch2];
        s1a += v.x; s2a += v.x * v.x;
        s1b += v.y; s2b += v.y * v.y;
    }
    __shared__ float a1[8][32][2], a2[8][32][2];
    a1[w][lane][0] = s1a; a1[w][lane][1] = s1b;
    a2[w][lane][0] = s2a; a2[w][lane][1] = s2b;
    __syncthreads();
    if (w == 0) {
#pragma unroll
        for (int t = 1; t < 8; t++) {
            s1a += a1[t][lane][0]; s1b += a1[t][lane][1];
            s2a += a2[t][lane][0]; s2b += a2[t][lane][1];
        }
        atomicAdd(&g_acc[65536 + g * 64 + ch2],     s1a);
        atomicAdd(&g_acc[65536 + g * 64 + ch2 + 1], s1b);
        atomicAdd(&g_acc[73728 + g * 64 + ch2],     s2a);
        atomicAdd(&g_acc[73728 + g * 64 + ch2 + 1], s2b);
    }
}

// ---------------- K8: finalize mean2/rstd2 --------------------------------------
__global__ void k_fin2() {
    int g = blockIdx.x, ch = threadIdx.x;      // 128 x 64
    int cnti = g_off[g + 1] - g_off[g]; if (cnti < 1) cnti = 1;
    float inv = 1.f / (float)cnti;
    float mean = g_acc[65536 + g * 64 + ch] * inv;
    float var  = fmaxf(g_acc[73728 + g * 64 + ch] * inv - mean * mean, 0.f);
    g_mean2[g * 64 + ch] = mean;
    g_rstd2[g * 64 + ch] = rsqrtf(var + EPS);
}

// ---------------- K9: out[perm[m]] = relu(norm2(h2)) . W3 + b3 -----------------
__global__ void k_final(const float* __restrict__ W3,
                        const float* __restrict__ b3,
                        float* __restrict__ out, int E) {
    __shared__ __align__(16) float sm[128 * 65];
    __shared__ float w3s[64];
    __shared__ int   sS[128];
    int tid = threadIdx.x;   // 128
    int m0  = blockIdx.x * 128;
    if (tid < 64) w3s[tid] = W3[tid];
    {
        int m = m0 + tid; if (m >= E) m = E - 1;
        sS[tid] = g_segS[m];
    }
    __syncthreads();
#pragma unroll
    for (int t = tid; t < 128 * 16; t += 128) {
        int rr = t >> 4, q = t & 15;
        int m = m0 + rr; if (m >= E) m = E - 1;
        float4 v  = __ldcs((const float4*)&g_h2[(size_t)m * 64 + q * 4]);
        int s = sS[rr];
        float4 mu = *(const float4*)&g_mean2[s * 64 + q * 4];
        float4 rs = *(const float4*)&g_rstd2[s * 64 + q * 4];
        float* d = &sm[rr * 65 + q * 4];
        d[0] = fmaxf((v.x - mu.x) * rs.x, 0.f);
        d[1] = fmaxf((v.y - mu.y) * rs.y, 0.f);
        d[2] = fmaxf((v.z - mu.z) * rs.z, 0.f);
        d[3] = fmaxf((v.w - mu.w) * rs.w, 0.f);
    }
    __syncthreads();
    int m = m0 + tid;
    if (m < E) {
        float acc = 0.f;
#pragma unroll
        for (int k = 0; k < 64; k++) acc += sm[tid * 65 + k] * w3s[k];
        out[g_perm[m]] = acc + b3[0];
    }
}

// ---------------- launch ---------------------------------------------------------
extern "C" void kernel_launch(void* const* d_in, const int* in_sizes, int n_in,
                              void* d_out, int out_size) {
    const float* emb = (const float*)d_in[0];
    const void*  ei  = d_in[1];
    const void*  bt  = d_in[2];
    const float* W1  = (const float*)d_in[3];
    // d_in[4] = b1 : cancels exactly through affine-free InstanceNorm
    const float* W2  = (const float*)d_in[5];
    // d_in[6] = b2 : cancels exactly through affine-free InstanceNorm
    const float* W3  = (const float*)d_in[7];
    const float* b3  = (const float*)d_in[8];
    float* out = (float*)d_out;

    int Nn = in_sizes[0] / 64;
    int E  = in_sizes[1] / 2;

    int nEdgeBlk = (E + 255) / 256;
    int nPqBlk   = ((Nn + 127) / 128) * 8;

    k_prep<<<176 + nEdgeBlk, 256>>>(ei, W1, W2, E, Nn);          // 1
    k_scan_node<<<1, 1024>>>(bt, E, Nn);                         // 2
    k_sp<<<nEdgeBlk + nPqBlk, 256>>>(bt, emb, E, Nn, nEdgeBlk);  // 3
    k_stats1a<<<dim3(128, 2, SPLIT1), 256>>>();                  // 4 (profiled)
    k_fin1<<<128, 256>>>();                                      // 5
    k_gemm2<<<(E + 127) / 128, 256>>>(E);                        // 6
    k_stats2a<<<dim3(128, SPLIT2), 256>>>();                     // 7
    k_fin2<<<128, 64>>>();                                       // 8
    k_final<<<(E + 127) / 128, 128>>>(W3, b3, out, E);           // 9
}